// round 2
// baseline (speedup 1.0000x reference)
#include <cuda_runtime.h>
#include <math.h>
#include <stdint.h>

// ---------------- problem constants ----------------
#define BATCH   2
#define SEQL    1024
#define DMODEL  1024
#define DINNER  2048
#define DSTATE  16
#define DCONV   4
#define DTRANK  64
#define NTOK    (BATCH * SEQL)          // 2048
#define XDBL_N  (DTRANK + 2 * DSTATE)   // 96

// ---------------- scratch (device globals; no allocs allowed) ----------------
__device__ float g_xz[(size_t)NTOK * 2 * DINNER];   // 2048 x 4096  (u_raw | z)
__device__ float g_u[(size_t)NTOK * DINNER];        // post conv+silu
__device__ float g_zs[(size_t)NTOK * DINNER];       // silu(z), precomputed
__device__ float g_xdbl[(size_t)NTOK * XDBL_N];     // [dt_lo(64) | B(16) | C(16)]
__device__ float g_delta[(size_t)NTOK * DINNER];    // softplus(dt_lo@W_dt + b_dt)
__device__ float g_y[(size_t)NTOK * DINNER];        // pre-output-proj activations

// ---------------- generic 128x128x8 SGEMM, 8x8 per thread ----------------
// C[M,N] = A[M,K] @ B[K,N], row-major with explicit leading dims.
// EPI==1: C = softplus(acc + bias[col])
template <int EPI>
__global__ __launch_bounds__(256) void sgemm128(
    const float* __restrict__ A, const float* __restrict__ B, float* __restrict__ C,
    int M, int N, int K, int lda, int ldb, int ldc, const float* __restrict__ bias)
{
    const int BM = 128, BN = 128, BK = 8;
    __shared__ float As[BK][BM];   // transposed A tile
    __shared__ float Bs[BK][BN];

    int tid = threadIdx.x;
    int bm = blockIdx.y, bn = blockIdx.x;

    const float* Ablk = A + (size_t)bm * BM * lda;
    const float* Bblk = B + (size_t)bn * BN;

    int arow = tid >> 1;            // 0..127
    int acol = (tid & 1) * 4;       // 0 or 4
    int brow = tid >> 5;            // 0..7
    int bcol = (tid & 31) * 4;      // 0..124

    int ty = tid >> 4, tx = tid & 15;

    float acc[8][8];
#pragma unroll
    for (int i = 0; i < 8; i++)
#pragma unroll
        for (int j = 0; j < 8; j++) acc[i][j] = 0.f;

    for (int k0 = 0; k0 < K; k0 += BK) {
        float4 av = *(const float4*)(Ablk + (size_t)arow * lda + k0 + acol);
        As[acol + 0][arow] = av.x;
        As[acol + 1][arow] = av.y;
        As[acol + 2][arow] = av.z;
        As[acol + 3][arow] = av.w;
        *(float4*)&Bs[brow][bcol] =
            *(const float4*)(Bblk + (size_t)(k0 + brow) * ldb + bcol);
        __syncthreads();

#pragma unroll
        for (int k = 0; k < BK; k++) {
            float a[8], b[8];
#pragma unroll
            for (int i = 0; i < 8; i++) a[i] = As[k][ty * 8 + i];
#pragma unroll
            for (int j = 0; j < 8; j++) b[j] = Bs[k][tx * 8 + j];
#pragma unroll
            for (int i = 0; i < 8; i++)
#pragma unroll
                for (int j = 0; j < 8; j++) acc[i][j] = fmaf(a[i], b[j], acc[i][j]);
        }
        __syncthreads();
    }

#pragma unroll
    for (int i = 0; i < 8; i++) {
        int r = bm * 128 + ty * 8 + i;
#pragma unroll
        for (int j = 0; j < 8; j++) {
            int c = bn * 128 + tx * 8 + j;
            float v = acc[i][j];
            if (EPI == 1) {
                v += bias[c];
                v = (v > 20.f) ? v : log1pf(expf(v));   // softplus
            }
            C[(size_t)r * ldc + c] = v;
        }
    }
}

// ---------------- zero fill ----------------
__global__ void zero_kernel(float* __restrict__ p, int n) {
    int i = blockIdx.x * blockDim.x + threadIdx.x;
    if (i < n) p[i] = 0.f;
}

// ---------------- x_dbl = u @ W_x (M=2048, N=96, K=2048), split-K=4 ----------------
__global__ __launch_bounds__(256) void gemm_xdbl(const float* __restrict__ Wx)
{
    const int BM = 32, BK = 32;
    __shared__ float As[BM][BK + 1];   // +1 pad: avoid 4-way bank conflict on As[row][k]
    __shared__ float Bs[BK][XDBL_N];

    int tid = threadIdx.x;
    int m0 = blockIdx.x * BM;
    int k0base = blockIdx.y * (DINNER / 4);   // 4-way split-K, 512 each
    int row = tid >> 3;            // 0..31
    int colg = (tid & 7) * 12;     // 0..84

    float acc[12];
#pragma unroll
    for (int j = 0; j < 12; j++) acc[j] = 0.f;

    for (int k0 = k0base; k0 < k0base + DINNER / 4; k0 += BK) {
        int ar = tid >> 3, ac = (tid & 7) * 4;
        float4 av = *(const float4*)(g_u + (size_t)(m0 + ar) * DINNER + k0 + ac);
        As[ar][ac + 0] = av.x; As[ar][ac + 1] = av.y;
        As[ar][ac + 2] = av.z; As[ar][ac + 3] = av.w;
#pragma unroll
        for (int t = 0; t < 3; t++) {
            int f = tid + t * 256;
            int br = (f * 4) / XDBL_N, bc = (f * 4) % XDBL_N;
            *(float4*)&Bs[br][bc] = *(const float4*)(Wx + (size_t)(k0 + br) * XDBL_N + bc);
        }
        __syncthreads();
#pragma unroll
        for (int k = 0; k < BK; k++) {
            float a = As[row][k];
#pragma unroll
            for (int j = 0; j < 12; j++) acc[j] = fmaf(a, Bs[k][colg + j], acc[j]);
        }
        __syncthreads();
    }
#pragma unroll
    for (int j = 0; j < 12; j++)
        atomicAdd(&g_xdbl[(size_t)(m0 + row) * XDBL_N + colg + j], acc[j]);
}

// ---------------- causal depthwise conv + SiLU, plus silu(z) ----------------
__global__ void conv_silu_gate(const float* __restrict__ ck, const float* __restrict__ cb)
{
    int idx = blockIdx.x * blockDim.x + threadIdx.x;
    if (idx >= NTOK * DINNER) return;
    int d  = idx & (DINNER - 1);
    int bt = idx >> 11;            // global token 0..2047
    int t  = bt & (SEQL - 1);      // position within sequence

    float acc = cb[d];
#pragma unroll
    for (int w = 0; w < DCONV; w++) {
        int tt = t - (DCONV - 1) + w;
        if (tt >= 0)
            acc = fmaf(ck[w * DINNER + d],
                       g_xz[(size_t)(bt - (DCONV - 1) + w) * (2 * DINNER) + d], acc);
    }
    g_u[idx] = acc / (1.f + __expf(-acc));                       // silu(conv)
    float z = g_xz[(size_t)bt * (2 * DINNER) + DINNER + d];
    g_zs[idx] = z / (1.f + __expf(-z));                          // silu(z)
}

// ---------------- selective-scan: 16 lanes per channel (one per state) ----------------
__global__ __launch_bounds__(256) void scan_kernel(
    const float* __restrict__ A_log, const float* __restrict__ Dp)
{
    int tid = threadIdx.x;
    int ch = blockIdx.x * 16 + (tid >> 4);   // 0..4095
    int n = tid & 15;
    int b = ch >> 11;
    int d = ch & (DINNER - 1);

    float a = -expf(A_log[d * DSTATE + n]);
    float Dd = Dp[d];
    float h = 0.f;

    const float* dptr = g_delta + (size_t)b * SEQL * DINNER + d;
    const float* uptr = g_u     + (size_t)b * SEQL * DINNER + d;
    const float* zptr = g_zs    + (size_t)b * SEQL * DINNER + d;
    float*       yptr = g_y     + (size_t)b * SEQL * DINNER + d;
    const float* xd   = g_xdbl  + (size_t)b * SEQL * XDBL_N;

    for (int t = 0; t < SEQL; t++) {
        float delta = dptr[(size_t)t * DINNER];
        float uv    = uptr[(size_t)t * DINNER];
        float Bn    = xd[t * XDBL_N + DTRANK + n];
        float Cn    = xd[t * XDBL_N + DTRANK + DSTATE + n];

        h = __expf(delta * a) * h + delta * uv * Bn;

        float p = h * Cn;
        p += __shfl_xor_sync(0xffffffffu, p, 8);
        p += __shfl_xor_sync(0xffffffffu, p, 4);
        p += __shfl_xor_sync(0xffffffffu, p, 2);
        p += __shfl_xor_sync(0xffffffffu, p, 1);

        if (n == 0)
            yptr[(size_t)t * DINNER] = (p + uv * Dd) * zptr[(size_t)t * DINNER];
    }
}

// ---------------- launch ----------------
extern "C" void kernel_launch(void* const* d_in, const int* in_sizes, int n_in,
                              void* d_out, int out_size)
{
    (void)in_sizes; (void)n_in; (void)out_size;
    const float* x     = (const float*)d_in[0];
    const float* W_in  = (const float*)d_in[1];
    const float* ck    = (const float*)d_in[2];
    const float* cb    = (const float*)d_in[3];
    const float* W_x   = (const float*)d_in[4];
    const float* W_dt  = (const float*)d_in[5];
    const float* b_dt  = (const float*)d_in[6];
    const float* W_out = (const float*)d_in[7];
    const float* A_log = (const float*)d_in[8];
    const float* Dp    = (const float*)d_in[9];
    float* out = (float*)d_out;

    float *p_xz, *p_xdbl, *p_delta, *p_y;
    cudaGetSymbolAddress((void**)&p_xz,    g_xz);
    cudaGetSymbolAddress((void**)&p_xdbl,  g_xdbl);
    cudaGetSymbolAddress((void**)&p_delta, g_delta);
    cudaGetSymbolAddress((void**)&p_y,     g_y);

    // 1) xz = x @ W_in     (2048 x 4096, K=1024)
    sgemm128<0><<<dim3(2 * DINNER / 128, NTOK / 128), 256>>>(
        x, W_in, p_xz, NTOK, 2 * DINNER, DMODEL, DMODEL, 2 * DINNER, 2 * DINNER, nullptr);

    // 2) causal depthwise conv + silu on u; silu(z)
    conv_silu_gate<<<(NTOK * DINNER) / 256, 256>>>(ck, cb);

    // 3) x_dbl = u @ W_x   (2048 x 96, K=2048) with split-K atomics
    zero_kernel<<<(NTOK * XDBL_N + 255) / 256, 256>>>(p_xdbl, NTOK * XDBL_N);
    gemm_xdbl<<<dim3(NTOK / 32, 4), 256>>>(W_x);

    // 4) delta = softplus(dt_lo @ W_dt + b_dt)   (2048 x 2048, K=64, lda=96)
    sgemm128<1><<<dim3(DINNER / 128, NTOK / 128), 256>>>(
        p_xdbl, W_dt, p_delta, NTOK, DINNER, DTRANK, XDBL_N, DINNER, DINNER, b_dt);

    // 5) selective scan + skip + gating -> g_y
    scan_kernel<<<(BATCH * DINNER) / 16, 256>>>(A_log, Dp);

    // 6) out = y @ W_out   (2048 x 1024, K=2048)
    sgemm128<0><<<dim3(DMODEL / 128, NTOK / 128), 256>>>(
        p_y, W_out, out, NTOK, DMODEL, DINNER, DINNER, DMODEL, DMODEL, nullptr);
}

// round 4
// speedup vs baseline: 1.3672x; 1.3672x over previous
#include <cuda_runtime.h>
#include <cuda_bf16.h>
#include <math.h>
#include <stdint.h>

// ---------------- problem constants ----------------
#define BATCH   2
#define SEQL    1024
#define DMODEL  1024
#define DINNER  2048
#define DSTATE  16
#define DCONV   4
#define DTRANK  64
#define NTOK    (BATCH * SEQL)          // 2048
#define XDBL_LD 128                     // padded (dt 0..63 | B 64..79 | C 80..95 | pad)

// ---------------- PTX helpers (portable: sm_80-era features only) ----------------
__device__ __forceinline__ uint32_t smem_to_u32(const void* p) {
    uint32_t a;
    asm("{ .reg .u64 t; cvta.to.shared.u64 t, %1; cvt.u32.u64 %0, t; }" : "=r"(a) : "l"(p));
    return a;
}
__device__ __forceinline__ void cpasync16(uint32_t s, const void* g) {
    asm volatile("cp.async.cg.shared.global [%0], [%1], 16;" :: "r"(s), "l"(g));
}
#define CP_COMMIT()  asm volatile("cp.async.commit_group;" ::: "memory")
#define CP_WAIT0()   asm volatile("cp.async.wait_group 0;" ::: "memory")
#define LDSM4(r, addr) \
    asm volatile("ldmatrix.sync.aligned.m8n8.x4.shared.b16 {%0,%1,%2,%3}, [%4];" \
        : "=r"((r)[0]), "=r"((r)[1]), "=r"((r)[2]), "=r"((r)[3]) : "r"(addr))

__device__ __forceinline__ void mma16816(float* d, const uint32_t* a, const uint32_t* b) {
    asm volatile(
        "mma.sync.aligned.m16n8k16.row.col.f32.bf16.bf16.f32 "
        "{%0,%1,%2,%3}, {%4,%5,%6,%7}, {%8,%9}, {%0,%1,%2,%3};"
        : "+f"(d[0]), "+f"(d[1]), "+f"(d[2]), "+f"(d[3])
        : "r"(a[0]), "r"(a[1]), "r"(a[2]), "r"(a[3]), "r"(b[0]), "r"(b[1]));
}

// swizzled byte offset of 16B chunk c in row r (row = 64 bytes = 4 chunks)
// conflict-free for 8-row ldmatrix tiles: chunk ^= (row>>1)&3
__device__ __forceinline__ uint32_t sw_off(int r, int c) {
    return (uint32_t)(r * 64 + ((c ^ ((r >> 1) & 3)) << 4));
}

// ---------------- scratch (device globals) ----------------
__device__ float g_xz[(size_t)NTOK * 2 * DINNER];     // (u_raw | z)
__device__ float g_u[(size_t)NTOK * DINNER];
__device__ float g_zs[(size_t)NTOK * DINNER];
__device__ float g_xdbl[(size_t)NTOK * XDBL_LD];
__device__ float g_delta[(size_t)NTOK * DINNER];

__device__ __nv_bfloat16 g_xh[(size_t)NTOK * DMODEL],   g_xl[(size_t)NTOK * DMODEL];
__device__ __nv_bfloat16 g_uh[(size_t)NTOK * DINNER],   g_ul[(size_t)NTOK * DINNER];
__device__ __nv_bfloat16 g_yh[(size_t)NTOK * DINNER],   g_yl[(size_t)NTOK * DINNER];
__device__ __nv_bfloat16 g_dth[(size_t)NTOK * DTRANK],  g_dtl[(size_t)NTOK * DTRANK];
// transposed+split weights: [N][K] row-major (K contiguous)
__device__ __nv_bfloat16 g_wint_h[(size_t)2 * DINNER * DMODEL], g_wint_l[(size_t)2 * DINNER * DMODEL];
__device__ __nv_bfloat16 g_wxt_h[(size_t)XDBL_LD * DINNER],     g_wxt_l[(size_t)XDBL_LD * DINNER];
__device__ __nv_bfloat16 g_wdtt_h[(size_t)DINNER * DTRANK],     g_wdtt_l[(size_t)DINNER * DTRANK];
__device__ __nv_bfloat16 g_wot_h[(size_t)DMODEL * DINNER],      g_wot_l[(size_t)DMODEL * DINNER];

// ---------------- mma.sync bf16-split GEMM ----------------
// C[M,N] = A[M,K] @ B[K,N], A row-major [M][K], B given transposed [N][K].
// 3-term split: Ah*Bh + Ah*Bl + Al*Bh with fp32 accum.
// EPI 0: store,  1: softplus(acc + bias[col]),  2: atomicAdd (split-K)
#define MG_SMEM (2 * 32768)
template <int EPI>
__global__ __launch_bounds__(256, 1) void mma_gemm(
    const __nv_bfloat16* __restrict__ Ah, const __nv_bfloat16* __restrict__ Al, int lda,
    const __nv_bfloat16* __restrict__ Bh, const __nv_bfloat16* __restrict__ Bl, int ldb,
    float* __restrict__ C, int ldc, int K, int KS, const float* __restrict__ bias)
{
    extern __shared__ char smem[];
    uint32_t sb = smem_to_u32(smem);
    const int tid = threadIdx.x, lane = tid & 31, wid = tid >> 5;
    const int wm = wid & 3, wn = wid >> 2;          // warp tile: rows wm*32, cols wn*64
    const int row0 = blockIdx.y * 128, col0 = blockIdx.x * 128;
    const int kper = K / KS;
    const int kbeg = blockIdx.z * kper;
    const int kn = kper >> 5;                        // 32-wide k tiles

    float acc[2][8][4];
#pragma unroll
    for (int i = 0; i < 2; i++)
#pragma unroll
        for (int j = 0; j < 8; j++)
#pragma unroll
            for (int r = 0; r < 4; r++) acc[i][j][r] = 0.f;

    // stage buffer offsets: Ah 0, Al 8K, Bh 16K, Bl 24K  (each 128 rows x 64B)
    auto load_stage = [&](int s, int k0) {
        uint32_t base = sb + s * 32768;
#pragma unroll
        for (int j = 0; j < 2; j++) {
            int idx = tid + j * 256;                 // 0..511
            int r = idx >> 2, c = idx & 3;
            uint32_t so = sw_off(r, c);
            size_t ao = (size_t)(row0 + r) * lda + k0 + c * 8;
            size_t bo = (size_t)(col0 + r) * ldb + k0 + c * 8;
            cpasync16(base + so,          Ah + ao);
            cpasync16(base + 8192 + so,   Al + ao);
            cpasync16(base + 16384 + so,  Bh + bo);
            cpasync16(base + 24576 + so,  Bl + bo);
        }
        CP_COMMIT();
    };

    load_stage(0, kbeg);

    const int a_row = wm * 32 + ((lane >> 3) & 1) * 8 + (lane & 7);   // + mi*16
    const int b_row = wn * 64 + (lane >> 4) * 8 + (lane & 7);         // + j*16

    for (int it = 0; it < kn; it++) {
        CP_WAIT0();
        __syncthreads();
        if (it + 1 < kn) load_stage((it + 1) & 1, kbeg + (it + 1) * 32);
        uint32_t base = sb + (it & 1) * 32768;
#pragma unroll
        for (int kk = 0; kk < 2; kk++) {
            uint32_t ah[2][4], al[2][4], bh[8][2], bl[8][2];
#pragma unroll
            for (int mi = 0; mi < 2; mi++) {
                int r = a_row + mi * 16;
                int c = kk * 2 + (lane >> 4);
                uint32_t so = sw_off(r, c);
                LDSM4(ah[mi], base + so);
                LDSM4(al[mi], base + 8192 + so);
            }
#pragma unroll
            for (int j = 0; j < 4; j++) {
                int r = b_row + j * 16;
                int c = kk * 2 + ((lane >> 3) & 1);
                uint32_t so = sw_off(r, c);
                uint32_t t[4];
                LDSM4(t, base + 16384 + so);
                bh[2 * j][0] = t[0]; bh[2 * j][1] = t[1];
                bh[2 * j + 1][0] = t[2]; bh[2 * j + 1][1] = t[3];
                LDSM4(t, base + 24576 + so);
                bl[2 * j][0] = t[0]; bl[2 * j][1] = t[1];
                bl[2 * j + 1][0] = t[2]; bl[2 * j + 1][1] = t[3];
            }
#pragma unroll
            for (int mi = 0; mi < 2; mi++)
#pragma unroll
                for (int nj = 0; nj < 8; nj++) {
                    mma16816(acc[mi][nj], ah[mi], bh[nj]);
                    mma16816(acc[mi][nj], ah[mi], bl[nj]);
                    mma16816(acc[mi][nj], al[mi], bh[nj]);
                }
        }
    }

    // epilogue: d-frag mapping: d0,d1 -> (row, col..col+1); d2,d3 -> (row+8, ..)
#pragma unroll
    for (int mi = 0; mi < 2; mi++) {
        int row = row0 + wm * 32 + mi * 16 + (lane >> 2);
#pragma unroll
        for (int nj = 0; nj < 8; nj++) {
            int col = col0 + wn * 64 + nj * 8 + (lane & 3) * 2;
            float* a = acc[mi][nj];
            if (EPI == 0) {
                *(float2*)&C[(size_t)row * ldc + col]       = make_float2(a[0], a[1]);
                *(float2*)&C[(size_t)(row + 8) * ldc + col] = make_float2(a[2], a[3]);
            } else if (EPI == 1) {
                float b0 = bias[col], b1 = bias[col + 1];
                float v0 = a[0] + b0, v1 = a[1] + b1, v2 = a[2] + b0, v3 = a[3] + b1;
                v0 = (v0 > 20.f) ? v0 : log1pf(expf(v0));
                v1 = (v1 > 20.f) ? v1 : log1pf(expf(v1));
                v2 = (v2 > 20.f) ? v2 : log1pf(expf(v2));
                v3 = (v3 > 20.f) ? v3 : log1pf(expf(v3));
                *(float2*)&C[(size_t)row * ldc + col]       = make_float2(v0, v1);
                *(float2*)&C[(size_t)(row + 8) * ldc + col] = make_float2(v2, v3);
            } else {
                atomicAdd(&C[(size_t)row * ldc + col],           a[0]);
                atomicAdd(&C[(size_t)row * ldc + col + 1],       a[1]);
                atomicAdd(&C[(size_t)(row + 8) * ldc + col],     a[2]);
                atomicAdd(&C[(size_t)(row + 8) * ldc + col + 1], a[3]);
            }
        }
    }
}

// ---------------- elementwise split (fp32 -> bf16 hi/lo) ----------------
__global__ void cvt_split(const float* __restrict__ src,
                          __nv_bfloat16* __restrict__ h, __nv_bfloat16* __restrict__ l, int n)
{
    int i = blockIdx.x * blockDim.x + threadIdx.x;
    if (i >= n) return;
    float v = src[i];
    __nv_bfloat16 hi = __float2bfloat16(v);
    h[i] = hi;
    l[i] = __float2bfloat16(v - __bfloat162float(hi));
}

// dt_lo slice of padded xdbl -> split arrays [2048][64]
__global__ void cvt_dt()
{
    int i = blockIdx.x * blockDim.x + threadIdx.x;   // < NTOK*64
    int t = i >> 6, c = i & 63;
    float v = g_xdbl[(size_t)t * XDBL_LD + c];
    __nv_bfloat16 hi = __float2bfloat16(v);
    g_dth[i] = hi;
    g_dtl[i] = __float2bfloat16(v - __bfloat162float(hi));
}

// ---------------- transpose + split:  W[K][N] -> T[Npad][K] (bf16 hi/lo, pad zero) ----------------
__global__ void transpose_split(const float* __restrict__ W, int K, int N,
                                __nv_bfloat16* __restrict__ Th, __nv_bfloat16* __restrict__ Tl)
{
    __shared__ float t[32][33];
    int bx = blockIdx.x, by = blockIdx.y;
    int tx = threadIdx.x, ty0 = threadIdx.y;
#pragma unroll
    for (int s = 0; s < 4; s++) {
        int ty = ty0 + s * 8;
        int col = bx * 32 + tx;          // n
        int row = by * 32 + ty;          // k
        t[ty][tx] = (col < N) ? W[(size_t)row * N + col] : 0.f;
    }
    __syncthreads();
#pragma unroll
    for (int s = 0; s < 4; s++) {
        int ty = ty0 + s * 8;
        int n = bx * 32 + ty;
        int k = by * 32 + tx;
        float v = t[tx][ty];
        __nv_bfloat16 hi = __float2bfloat16(v);
        Th[(size_t)n * K + k] = hi;
        Tl[(size_t)n * K + k] = __float2bfloat16(v - __bfloat162float(hi));
    }
}

// ---------------- zero fill ----------------
__global__ void zero_kernel(float* __restrict__ p, int n) {
    int i = blockIdx.x * blockDim.x + threadIdx.x;
    if (i < n) p[i] = 0.f;
}

// ---------------- conv + SiLU (+ bf16 split of u) + silu(z) ----------------
__global__ void conv_silu_gate(const float* __restrict__ ck, const float* __restrict__ cb)
{
    int idx = blockIdx.x * blockDim.x + threadIdx.x;
    if (idx >= NTOK * DINNER) return;
    int d  = idx & (DINNER - 1);
    int bt = idx >> 11;
    int t  = bt & (SEQL - 1);

    float acc = cb[d];
#pragma unroll
    for (int w = 0; w < DCONV; w++) {
        int tt = t - (DCONV - 1) + w;
        if (tt >= 0)
            acc = fmaf(ck[w * DINNER + d],
                       g_xz[(size_t)(bt - (DCONV - 1) + w) * (2 * DINNER) + d], acc);
    }
    float u = acc / (1.f + __expf(-acc));
    g_u[idx] = u;
    __nv_bfloat16 hi = __float2bfloat16(u);
    g_uh[idx] = hi;
    g_ul[idx] = __float2bfloat16(u - __bfloat162float(hi));
    float z = g_xz[(size_t)bt * (2 * DINNER) + DINNER + d];
    g_zs[idx] = z / (1.f + __expf(-z));
}

// ---------------- selective scan (16 lanes per channel), writes split y ----------------
__global__ __launch_bounds__(256) void scan_kernel(
    const float* __restrict__ A_log, const float* __restrict__ Dp)
{
    int tid = threadIdx.x;
    int ch = blockIdx.x * 16 + (tid >> 4);
    int n = tid & 15;
    int b = ch >> 11;
    int d = ch & (DINNER - 1);

    float a = -expf(A_log[d * DSTATE + n]);
    float Dd = Dp[d];
    float h = 0.f;

    const float* dptr = g_delta + (size_t)b * SEQL * DINNER + d;
    const float* uptr = g_u     + (size_t)b * SEQL * DINNER + d;
    const float* zptr = g_zs    + (size_t)b * SEQL * DINNER + d;
    __nv_bfloat16* yh = g_yh + (size_t)b * SEQL * DINNER + d;
    __nv_bfloat16* yl = g_yl + (size_t)b * SEQL * DINNER + d;
    const float* xd = g_xdbl + (size_t)b * SEQL * XDBL_LD;

    for (int t = 0; t < SEQL; t++) {
        float delta = dptr[(size_t)t * DINNER];
        float uv    = uptr[(size_t)t * DINNER];
        float Bn    = xd[t * XDBL_LD + DTRANK + n];
        float Cn    = xd[t * XDBL_LD + DTRANK + DSTATE + n];

        h = __expf(delta * a) * h + delta * uv * Bn;

        float p = h * Cn;
        p += __shfl_xor_sync(0xffffffffu, p, 8);
        p += __shfl_xor_sync(0xffffffffu, p, 4);
        p += __shfl_xor_sync(0xffffffffu, p, 2);
        p += __shfl_xor_sync(0xffffffffu, p, 1);

        if (n == 0) {
            float v = (p + uv * Dd) * zptr[(size_t)t * DINNER];
            __nv_bfloat16 hi = __float2bfloat16(v);
            yh[(size_t)t * DINNER] = hi;
            yl[(size_t)t * DINNER] = __float2bfloat16(v - __bfloat162float(hi));
        }
    }
}

// ---------------- launch ----------------
extern "C" void kernel_launch(void* const* d_in, const int* in_sizes, int n_in,
                              void* d_out, int out_size)
{
    (void)in_sizes; (void)n_in; (void)out_size;
    const float* x     = (const float*)d_in[0];
    const float* W_in  = (const float*)d_in[1];
    const float* ck    = (const float*)d_in[2];
    const float* cb    = (const float*)d_in[3];
    const float* W_x   = (const float*)d_in[4];
    const float* W_dt  = (const float*)d_in[5];
    const float* b_dt  = (const float*)d_in[6];
    const float* W_out = (const float*)d_in[7];
    const float* A_log = (const float*)d_in[8];
    const float* Dp    = (const float*)d_in[9];
    float* out = (float*)d_out;

    cudaFuncSetAttribute(mma_gemm<0>, cudaFuncAttributeMaxDynamicSharedMemorySize, MG_SMEM);
    cudaFuncSetAttribute(mma_gemm<1>, cudaFuncAttributeMaxDynamicSharedMemorySize, MG_SMEM);
    cudaFuncSetAttribute(mma_gemm<2>, cudaFuncAttributeMaxDynamicSharedMemorySize, MG_SMEM);

    float *p_xz, *p_xdbl, *p_delta;
    cudaGetSymbolAddress((void**)&p_xz,    g_xz);
    cudaGetSymbolAddress((void**)&p_xdbl,  g_xdbl);
    cudaGetSymbolAddress((void**)&p_delta, g_delta);
    __nv_bfloat16 *xh, *xl, *uh, *ul, *yh, *yl, *dth, *dtl;
    __nv_bfloat16 *winh, *winl, *wxth, *wxtl, *wdtth, *wdttl, *woth, *wotl;
    cudaGetSymbolAddress((void**)&xh, g_xh);     cudaGetSymbolAddress((void**)&xl, g_xl);
    cudaGetSymbolAddress((void**)&uh, g_uh);     cudaGetSymbolAddress((void**)&ul, g_ul);
    cudaGetSymbolAddress((void**)&yh, g_yh);     cudaGetSymbolAddress((void**)&yl, g_yl);
    cudaGetSymbolAddress((void**)&dth, g_dth);   cudaGetSymbolAddress((void**)&dtl, g_dtl);
    cudaGetSymbolAddress((void**)&winh, g_wint_h);  cudaGetSymbolAddress((void**)&winl, g_wint_l);
    cudaGetSymbolAddress((void**)&wxth, g_wxt_h);   cudaGetSymbolAddress((void**)&wxtl, g_wxt_l);
    cudaGetSymbolAddress((void**)&wdtth, g_wdtt_h); cudaGetSymbolAddress((void**)&wdttl, g_wdtt_l);
    cudaGetSymbolAddress((void**)&woth, g_wot_h);   cudaGetSymbolAddress((void**)&wotl, g_wot_l);

    // ---- prepare operands ----
    cvt_split<<<(NTOK * DMODEL + 255) / 256, 256>>>(x, xh, xl, NTOK * DMODEL);
    transpose_split<<<dim3(2 * DINNER / 32, DMODEL / 32), dim3(32, 8)>>>(W_in, DMODEL, 2 * DINNER, winh, winl);

    // 1) xz = x @ W_in : M=2048, N=4096, K=1024
    mma_gemm<0><<<dim3(32, 16, 1), 256, MG_SMEM>>>(
        xh, xl, DMODEL, winh, winl, DMODEL, p_xz, 2 * DINNER, DMODEL, 1, nullptr);

    // 2) conv + silu + splits
    conv_silu_gate<<<(NTOK * DINNER) / 256, 256>>>(ck, cb);

    // 3) x_dbl = u @ W_x : M=2048, N=128(pad of 96), K=2048, split-K=8 atomics
    zero_kernel<<<(NTOK * XDBL_LD) / 256, 256>>>(p_xdbl, NTOK * XDBL_LD);
    transpose_split<<<dim3(XDBL_LD / 32, DINNER / 32), dim3(32, 8)>>>(W_x, DINNER, DTRANK + 2 * DSTATE, wxth, wxtl);
    mma_gemm<2><<<dim3(1, 16, 8), 256, MG_SMEM>>>(
        uh, ul, DINNER, wxth, wxtl, DINNER, p_xdbl, XDBL_LD, DINNER, 8, nullptr);

    // 4) delta = softplus(dt_lo @ W_dt + b_dt) : M=2048, N=2048, K=64
    cvt_dt<<<(NTOK * DTRANK) / 256, 256>>>();
    transpose_split<<<dim3(DINNER / 32, DTRANK / 32), dim3(32, 8)>>>(W_dt, DTRANK, DINNER, wdtth, wdttl);
    mma_gemm<1><<<dim3(16, 16, 1), 256, MG_SMEM>>>(
        dth, dtl, DTRANK, wdtth, wdttl, DTRANK, p_delta, DINNER, DTRANK, 1, b_dt);

    // 5) selective scan + skip + gating -> split y
    scan_kernel<<<(BATCH * DINNER) / 16, 256>>>(A_log, Dp);

    // 6) out = y @ W_out : M=2048, N=1024, K=2048
    transpose_split<<<dim3(DMODEL / 32, DINNER / 32), dim3(32, 8)>>>(W_out, DINNER, DMODEL, woth, wotl);
    mma_gemm<0><<<dim3(8, 16, 1), 256, MG_SMEM>>>(
        yh, yl, DINNER, woth, wotl, DINNER, out, DMODEL, DINNER, 1, nullptr);
}

// round 5
// speedup vs baseline: 1.7680x; 1.2932x over previous
#include <cuda_runtime.h>
#include <cuda_bf16.h>
#include <math.h>
#include <stdint.h>

// ---------------- problem constants ----------------
#define BATCH   2
#define SEQL    1024
#define DMODEL  1024
#define DINNER  2048
#define DSTATE  16
#define DCONV   4
#define DTRANK  64
#define NTOK    (BATCH * SEQL)          // 2048
#define XDBL_LD 128                     // padded (dt 0..63 | B 64..79 | C 80..95 | pad)

// ---------------- PTX helpers (portable: sm_80-era features only) ----------------
__device__ __forceinline__ uint32_t smem_to_u32(const void* p) {
    uint32_t a;
    asm("{ .reg .u64 t; cvta.to.shared.u64 t, %1; cvt.u32.u64 %0, t; }" : "=r"(a) : "l"(p));
    return a;
}
__device__ __forceinline__ void cpasync16(uint32_t s, const void* g) {
    asm volatile("cp.async.cg.shared.global [%0], [%1], 16;" :: "r"(s), "l"(g));
}
#define CP_COMMIT()  asm volatile("cp.async.commit_group;" ::: "memory")
#define CP_WAIT0()   asm volatile("cp.async.wait_group 0;" ::: "memory")
#define CP_WAIT1()   asm volatile("cp.async.wait_group 1;" ::: "memory")
#define LDSM4(r, addr) \
    asm volatile("ldmatrix.sync.aligned.m8n8.x4.shared.b16 {%0,%1,%2,%3}, [%4];" \
        : "=r"((r)[0]), "=r"((r)[1]), "=r"((r)[2]), "=r"((r)[3]) : "r"(addr))

__device__ __forceinline__ void mma16816(float* d, const uint32_t* a, const uint32_t* b) {
    asm volatile(
        "mma.sync.aligned.m16n8k16.row.col.f32.bf16.bf16.f32 "
        "{%0,%1,%2,%3}, {%4,%5,%6,%7}, {%8,%9}, {%0,%1,%2,%3};"
        : "+f"(d[0]), "+f"(d[1]), "+f"(d[2]), "+f"(d[3])
        : "r"(a[0]), "r"(a[1]), "r"(a[2]), "r"(a[3]), "r"(b[0]), "r"(b[1]));
}

// swizzled byte offset of 16B chunk c in row r (row = 64 bytes = 4 chunks)
__device__ __forceinline__ uint32_t sw_off(int r, int c) {
    return (uint32_t)(r * 64 + ((c ^ ((r >> 1) & 3)) << 4));
}

// ---------------- scratch (device globals) ----------------
__device__ float g_xz[(size_t)NTOK * 2 * DINNER];     // (u_raw | z)
__device__ float g_u[(size_t)NTOK * DINNER];
__device__ float g_zs[(size_t)NTOK * DINNER];
__device__ float g_xdbl[(size_t)NTOK * XDBL_LD];
__device__ float g_delta[(size_t)NTOK * DINNER];

__device__ __nv_bfloat16 g_xh[(size_t)NTOK * DMODEL],   g_xl[(size_t)NTOK * DMODEL];
__device__ __nv_bfloat16 g_uh[(size_t)NTOK * DINNER],   g_ul[(size_t)NTOK * DINNER];
__device__ __nv_bfloat16 g_yh[(size_t)NTOK * DINNER],   g_yl[(size_t)NTOK * DINNER];
__device__ __nv_bfloat16 g_dth[(size_t)NTOK * DTRANK],  g_dtl[(size_t)NTOK * DTRANK];
// transposed+split weights: [N][K] row-major (K contiguous)
__device__ __nv_bfloat16 g_wint_h[(size_t)2 * DINNER * DMODEL], g_wint_l[(size_t)2 * DINNER * DMODEL];
__device__ __nv_bfloat16 g_wxt_h[(size_t)XDBL_LD * DINNER],     g_wxt_l[(size_t)XDBL_LD * DINNER];
__device__ __nv_bfloat16 g_wdtt_h[(size_t)DINNER * DTRANK],     g_wdtt_l[(size_t)DINNER * DTRANK];
__device__ __nv_bfloat16 g_wot_h[(size_t)DMODEL * DINNER],      g_wot_l[(size_t)DMODEL * DINNER];

// ---------------- mma.sync bf16-split GEMM, 3-stage pipeline ----------------
// C[M,N] = A[M,K] @ B[K,N], A row-major [M][K], B given transposed [N][K].
// 3-term split: Ah*Bh + Ah*Bl + Al*Bh, fp32 accum.
// EPI 0: store, 1: softplus(acc+bias[col]), 2: atomicAdd (split-K)
#define MG_SMEM (3 * 32768)
template <int EPI>
__global__ __launch_bounds__(256, 2) void mma_gemm(
    const __nv_bfloat16* __restrict__ Ah, const __nv_bfloat16* __restrict__ Al, int lda,
    const __nv_bfloat16* __restrict__ Bh, const __nv_bfloat16* __restrict__ Bl, int ldb,
    float* __restrict__ C, int ldc, int K, int KS, const float* __restrict__ bias)
{
    extern __shared__ char smem[];
    uint32_t sb = smem_to_u32(smem);
    const int tid = threadIdx.x, lane = tid & 31, wid = tid >> 5;
    const int wm = wid & 3, wn = wid >> 2;          // warp tile: rows wm*32, cols wn*64
    const int row0 = blockIdx.y * 128, col0 = blockIdx.x * 128;
    const int kper = K / KS;
    const int kbeg = blockIdx.z * kper;
    const int kn = kper >> 5;                        // 32-wide k tiles

    float acc[2][8][4];
#pragma unroll
    for (int i = 0; i < 2; i++)
#pragma unroll
        for (int j = 0; j < 8; j++)
#pragma unroll
            for (int r = 0; r < 4; r++) acc[i][j][r] = 0.f;

    // stage buffer: Ah 0, Al 8K, Bh 16K, Bl 24K  (each 128 rows x 64B)
    auto load_stage = [&](int s, int k0) {
        uint32_t base = sb + s * 32768;
#pragma unroll
        for (int j = 0; j < 2; j++) {
            int idx = tid + j * 256;                 // 0..511
            int r = idx >> 2, c = idx & 3;
            uint32_t so = sw_off(r, c);
            size_t ao = (size_t)(row0 + r) * lda + k0 + c * 8;
            size_t bo = (size_t)(col0 + r) * ldb + k0 + c * 8;
            cpasync16(base + so,          Ah + ao);
            cpasync16(base + 8192 + so,   Al + ao);
            cpasync16(base + 16384 + so,  Bh + bo);
            cpasync16(base + 24576 + so,  Bl + bo);
        }
        CP_COMMIT();
    };

    load_stage(0, kbeg);
    if (kn > 1) load_stage(1, kbeg + 32);

    const int a_row = wm * 32 + ((lane >> 3) & 1) * 8 + (lane & 7);   // + mi*16
    const int b_row = wn * 64 + (lane >> 4) * 8 + (lane & 7);         // + j*16

    for (int it = 0; it < kn; it++) {
        if (it + 1 < kn) CP_WAIT1(); else CP_WAIT0();
        __syncthreads();
        if (it + 2 < kn) load_stage((it + 2) % 3, kbeg + (it + 2) * 32);
        uint32_t base = sb + (it % 3) * 32768;
#pragma unroll
        for (int kk = 0; kk < 2; kk++) {
            uint32_t ah[2][4], al[2][4], bh[8][2], bl[8][2];
#pragma unroll
            for (int mi = 0; mi < 2; mi++) {
                int r = a_row + mi * 16;
                int c = kk * 2 + (lane >> 4);
                uint32_t so = sw_off(r, c);
                LDSM4(ah[mi], base + so);
                LDSM4(al[mi], base + 8192 + so);
            }
#pragma unroll
            for (int j = 0; j < 4; j++) {
                int r = b_row + j * 16;
                int c = kk * 2 + ((lane >> 3) & 1);
                uint32_t so = sw_off(r, c);
                uint32_t t[4];
                LDSM4(t, base + 16384 + so);
                bh[2 * j][0] = t[0]; bh[2 * j][1] = t[1];
                bh[2 * j + 1][0] = t[2]; bh[2 * j + 1][1] = t[3];
                LDSM4(t, base + 24576 + so);
                bl[2 * j][0] = t[0]; bl[2 * j][1] = t[1];
                bl[2 * j + 1][0] = t[2]; bl[2 * j + 1][1] = t[3];
            }
#pragma unroll
            for (int mi = 0; mi < 2; mi++)
#pragma unroll
                for (int nj = 0; nj < 8; nj++) {
                    mma16816(acc[mi][nj], ah[mi], bh[nj]);
                    mma16816(acc[mi][nj], ah[mi], bl[nj]);
                    mma16816(acc[mi][nj], al[mi], bh[nj]);
                }
        }
    }

#pragma unroll
    for (int mi = 0; mi < 2; mi++) {
        int row = row0 + wm * 32 + mi * 16 + (lane >> 2);
#pragma unroll
        for (int nj = 0; nj < 8; nj++) {
            int col = col0 + wn * 64 + nj * 8 + (lane & 3) * 2;
            float* a = acc[mi][nj];
            if (EPI == 0) {
                *(float2*)&C[(size_t)row * ldc + col]       = make_float2(a[0], a[1]);
                *(float2*)&C[(size_t)(row + 8) * ldc + col] = make_float2(a[2], a[3]);
            } else if (EPI == 1) {
                float b0 = bias[col], b1 = bias[col + 1];
                float v0 = a[0] + b0, v1 = a[1] + b1, v2 = a[2] + b0, v3 = a[3] + b1;
                v0 = (v0 > 20.f) ? v0 : log1pf(expf(v0));
                v1 = (v1 > 20.f) ? v1 : log1pf(expf(v1));
                v2 = (v2 > 20.f) ? v2 : log1pf(expf(v2));
                v3 = (v3 > 20.f) ? v3 : log1pf(expf(v3));
                *(float2*)&C[(size_t)row * ldc + col]       = make_float2(v0, v1);
                *(float2*)&C[(size_t)(row + 8) * ldc + col] = make_float2(v2, v3);
            } else {
                atomicAdd(&C[(size_t)row * ldc + col],           a[0]);
                atomicAdd(&C[(size_t)row * ldc + col + 1],       a[1]);
                atomicAdd(&C[(size_t)(row + 8) * ldc + col],     a[2]);
                atomicAdd(&C[(size_t)(row + 8) * ldc + col + 1], a[3]);
            }
        }
    }
}

// ---------------- elementwise split (fp32 -> bf16 hi/lo) ----------------
__global__ void cvt_split(const float* __restrict__ src,
                          __nv_bfloat16* __restrict__ h, __nv_bfloat16* __restrict__ l, int n)
{
    int i = blockIdx.x * blockDim.x + threadIdx.x;
    if (i >= n) return;
    float v = src[i];
    __nv_bfloat16 hi = __float2bfloat16(v);
    h[i] = hi;
    l[i] = __float2bfloat16(v - __bfloat162float(hi));
}

// dt_lo slice of padded xdbl -> split arrays [2048][64]
__global__ void cvt_dt()
{
    int i = blockIdx.x * blockDim.x + threadIdx.x;   // < NTOK*64
    int t = i >> 6, c = i & 63;
    float v = g_xdbl[(size_t)t * XDBL_LD + c];
    __nv_bfloat16 hi = __float2bfloat16(v);
    g_dth[i] = hi;
    g_dtl[i] = __float2bfloat16(v - __bfloat162float(hi));
}

// ---------------- transpose + split:  W[K][N] -> T[Npad][K] (bf16 hi/lo, pad zero) ----------------
__global__ void transpose_split(const float* __restrict__ W, int K, int N,
                                __nv_bfloat16* __restrict__ Th, __nv_bfloat16* __restrict__ Tl)
{
    __shared__ float t[32][33];
    int bx = blockIdx.x, by = blockIdx.y;
    int tx = threadIdx.x, ty0 = threadIdx.y;
#pragma unroll
    for (int s = 0; s < 4; s++) {
        int ty = ty0 + s * 8;
        int col = bx * 32 + tx;          // n
        int row = by * 32 + ty;          // k
        t[ty][tx] = (col < N) ? W[(size_t)row * N + col] : 0.f;
    }
    __syncthreads();
#pragma unroll
    for (int s = 0; s < 4; s++) {
        int ty = ty0 + s * 8;
        int n = bx * 32 + ty;
        int k = by * 32 + tx;
        float v = t[tx][ty];
        __nv_bfloat16 hi = __float2bfloat16(v);
        Th[(size_t)n * K + k] = hi;
        Tl[(size_t)n * K + k] = __float2bfloat16(v - __bfloat162float(hi));
    }
}

// ---------------- zero fill ----------------
__global__ void zero_kernel(float* __restrict__ p, int n) {
    int i = blockIdx.x * blockDim.x + threadIdx.x;
    if (i < n) p[i] = 0.f;
}

// ---------------- conv + SiLU (+ bf16 split of u) + silu(z) ----------------
__global__ void conv_silu_gate(const float* __restrict__ ck, const float* __restrict__ cb)
{
    int idx = blockIdx.x * blockDim.x + threadIdx.x;
    if (idx >= NTOK * DINNER) return;
    int d  = idx & (DINNER - 1);
    int bt = idx >> 11;
    int t  = bt & (SEQL - 1);

    float acc = cb[d];
#pragma unroll
    for (int w = 0; w < DCONV; w++) {
        int tt = t - (DCONV - 1) + w;
        if (tt >= 0)
            acc = fmaf(ck[w * DINNER + d],
                       g_xz[(size_t)(bt - (DCONV - 1) + w) * (2 * DINNER) + d], acc);
    }
    float u = acc / (1.f + __expf(-acc));
    g_u[idx] = u;
    __nv_bfloat16 hi = __float2bfloat16(u);
    g_uh[idx] = hi;
    g_ul[idx] = __float2bfloat16(u - __bfloat162float(hi));
    float z = g_xz[(size_t)bt * (2 * DINNER) + DINNER + d];
    g_zs[idx] = z / (1.f + __expf(-z));
}

// ---------------- selective scan, software-pipelined loads ----------------
__global__ __launch_bounds__(256) void scan_kernel(
    const float* __restrict__ A_log, const float* __restrict__ Dp)
{
    int tid = threadIdx.x;
    int ch = blockIdx.x * 16 + (tid >> 4);
    int n = tid & 15;
    int b = ch >> 11;
    int d = ch & (DINNER - 1);

    float a = -expf(A_log[d * DSTATE + n]);
    float Dd = Dp[d];
    float h = 0.f;

    const float* dptr = g_delta + (size_t)b * SEQL * DINNER + d;
    const float* uptr = g_u     + (size_t)b * SEQL * DINNER + d;
    const float* zptr = g_zs    + (size_t)b * SEQL * DINNER + d;
    __nv_bfloat16* yh = g_yh + (size_t)b * SEQL * DINNER + d;
    __nv_bfloat16* yl = g_yl + (size_t)b * SEQL * DINNER + d;
    const float* xd = g_xdbl + (size_t)b * SEQL * XDBL_LD;

    float d_c = dptr[0];
    float u_c = uptr[0];
    float B_c = xd[DTRANK + n];
    float C_c = xd[DTRANK + DSTATE + n];
    float z_c = zptr[0];

#pragma unroll 2
    for (int t = 0; t < SEQL; t++) {
        int tn = (t + 1 < SEQL) ? t + 1 : t;
        // prefetch next iteration (independent of the recurrence chain)
        float d_n = dptr[(size_t)tn * DINNER];
        float u_n = uptr[(size_t)tn * DINNER];
        float B_n = xd[tn * XDBL_LD + DTRANK + n];
        float C_n = xd[tn * XDBL_LD + DTRANK + DSTATE + n];
        float z_n = zptr[(size_t)tn * DINNER];

        h = __expf(d_c * a) * h + d_c * u_c * B_c;

        float p = h * C_c;
        p += __shfl_xor_sync(0xffffffffu, p, 8);
        p += __shfl_xor_sync(0xffffffffu, p, 4);
        p += __shfl_xor_sync(0xffffffffu, p, 2);
        p += __shfl_xor_sync(0xffffffffu, p, 1);

        if (n == 0) {
            float v = (p + u_c * Dd) * z_c;
            __nv_bfloat16 hi = __float2bfloat16(v);
            yh[(size_t)t * DINNER] = hi;
            yl[(size_t)t * DINNER] = __float2bfloat16(v - __bfloat162float(hi));
        }
        d_c = d_n; u_c = u_n; B_c = B_n; C_c = C_n; z_c = z_n;
    }
}

// ---------------- launch ----------------
extern "C" void kernel_launch(void* const* d_in, const int* in_sizes, int n_in,
                              void* d_out, int out_size)
{
    (void)in_sizes; (void)n_in; (void)out_size;
    const float* x     = (const float*)d_in[0];
    const float* W_in  = (const float*)d_in[1];
    const float* ck    = (const float*)d_in[2];
    const float* cb    = (const float*)d_in[3];
    const float* W_x   = (const float*)d_in[4];
    const float* W_dt  = (const float*)d_in[5];
    const float* b_dt  = (const float*)d_in[6];
    const float* W_out = (const float*)d_in[7];
    const float* A_log = (const float*)d_in[8];
    const float* Dp    = (const float*)d_in[9];
    float* out = (float*)d_out;

    cudaFuncSetAttribute(mma_gemm<0>, cudaFuncAttributeMaxDynamicSharedMemorySize, MG_SMEM);
    cudaFuncSetAttribute(mma_gemm<1>, cudaFuncAttributeMaxDynamicSharedMemorySize, MG_SMEM);
    cudaFuncSetAttribute(mma_gemm<2>, cudaFuncAttributeMaxDynamicSharedMemorySize, MG_SMEM);

    float *p_xz, *p_xdbl, *p_delta;
    cudaGetSymbolAddress((void**)&p_xz,    g_xz);
    cudaGetSymbolAddress((void**)&p_xdbl,  g_xdbl);
    cudaGetSymbolAddress((void**)&p_delta, g_delta);
    __nv_bfloat16 *xh, *xl, *uh, *ul, *yh, *yl, *dth, *dtl;
    __nv_bfloat16 *winh, *winl, *wxth, *wxtl, *wdtth, *wdttl, *woth, *wotl;
    cudaGetSymbolAddress((void**)&xh, g_xh);     cudaGetSymbolAddress((void**)&xl, g_xl);
    cudaGetSymbolAddress((void**)&uh, g_uh);     cudaGetSymbolAddress((void**)&ul, g_ul);
    cudaGetSymbolAddress((void**)&yh, g_yh);     cudaGetSymbolAddress((void**)&yl, g_yl);
    cudaGetSymbolAddress((void**)&dth, g_dth);   cudaGetSymbolAddress((void**)&dtl, g_dtl);
    cudaGetSymbolAddress((void**)&winh, g_wint_h);  cudaGetSymbolAddress((void**)&winl, g_wint_l);
    cudaGetSymbolAddress((void**)&wxth, g_wxt_h);   cudaGetSymbolAddress((void**)&wxtl, g_wxt_l);
    cudaGetSymbolAddress((void**)&wdtth, g_wdtt_h); cudaGetSymbolAddress((void**)&wdttl, g_wdtt_l);
    cudaGetSymbolAddress((void**)&woth, g_wot_h);   cudaGetSymbolAddress((void**)&wotl, g_wot_l);

    // launch #1..#3: prep (so that launch #4 = big GEMM lands in the ncu slot)
    cvt_split<<<(NTOK * DMODEL + 255) / 256, 256>>>(x, xh, xl, NTOK * DMODEL);
    transpose_split<<<dim3(2 * DINNER / 32, DMODEL / 32), dim3(32, 8)>>>(W_in, DMODEL, 2 * DINNER, winh, winl);
    transpose_split<<<dim3(DMODEL / 32, DINNER / 32), dim3(32, 8)>>>(W_out, DINNER, DMODEL, woth, wotl);

    // launch #4: xz = x @ W_in : M=2048, N=4096, K=1024
    mma_gemm<0><<<dim3(32, 16, 1), 256, MG_SMEM>>>(
        xh, xl, DMODEL, winh, winl, DMODEL, p_xz, 2 * DINNER, DMODEL, 1, nullptr);

    // conv + silu + splits
    conv_silu_gate<<<(NTOK * DINNER) / 256, 256>>>(ck, cb);

    // x_dbl = u @ W_x : M=2048, N=128(pad of 96), K=2048, split-K=8 atomics
    zero_kernel<<<(NTOK * XDBL_LD) / 256, 256>>>(p_xdbl, NTOK * XDBL_LD);
    transpose_split<<<dim3(XDBL_LD / 32, DINNER / 32), dim3(32, 8)>>>(W_x, DINNER, DTRANK + 2 * DSTATE, wxth, wxtl);
    mma_gemm<2><<<dim3(1, 16, 8), 256, MG_SMEM>>>(
        uh, ul, DINNER, wxth, wxtl, DINNER, p_xdbl, XDBL_LD, DINNER, 8, nullptr);

    // delta = softplus(dt_lo @ W_dt + b_dt) : M=2048, N=2048, K=64
    cvt_dt<<<(NTOK * DTRANK) / 256, 256>>>();
    transpose_split<<<dim3(DINNER / 32, DTRANK / 32), dim3(32, 8)>>>(W_dt, DTRANK, DINNER, wdtth, wdttl);
    mma_gemm<1><<<dim3(16, 16, 1), 256, MG_SMEM>>>(
        dth, dtl, DTRANK, wdtth, wdttl, DTRANK, p_delta, DINNER, DTRANK, 1, b_dt);

    // selective scan + skip + gating -> split y
    scan_kernel<<<(BATCH * DINNER) / 16, 256>>>(A_log, Dp);

    // out = y @ W_out : M=2048, N=1024, K=2048
    mma_gemm<0><<<dim3(8, 16, 1), 256, MG_SMEM>>>(
        yh, yl, DINNER, woth, wotl, DINNER, out, DMODEL, DINNER, 1, nullptr);
}

// round 6
// speedup vs baseline: 2.7943x; 1.5805x over previous
#include <cuda_runtime.h>
#include <cuda_bf16.h>
#include <math.h>
#include <stdint.h>

// ---------------- problem constants ----------------
#define BATCH   2
#define SEQL    1024
#define DMODEL  1024
#define DINNER  2048
#define DSTATE  16
#define DCONV   4
#define DTRANK  64
#define NTOK    (BATCH * SEQL)          // 2048
#define XDBL_LD 128                     // padded (dt 0..63 | B 64..79 | C 80..95 | pad)
#define NCHUNK  8
#define CLEN    (SEQL / NCHUNK)         // 128

// ---------------- PTX helpers (portable: sm_80-era features only) ----------------
__device__ __forceinline__ uint32_t smem_to_u32(const void* p) {
    uint32_t a;
    asm("{ .reg .u64 t; cvta.to.shared.u64 t, %1; cvt.u32.u64 %0, t; }" : "=r"(a) : "l"(p));
    return a;
}
__device__ __forceinline__ void cpasync16(uint32_t s, const void* g) {
    asm volatile("cp.async.cg.shared.global [%0], [%1], 16;" :: "r"(s), "l"(g));
}
#define CP_COMMIT()  asm volatile("cp.async.commit_group;" ::: "memory")
#define CP_WAIT0()   asm volatile("cp.async.wait_group 0;" ::: "memory")
#define CP_WAIT1()   asm volatile("cp.async.wait_group 1;" ::: "memory")
#define LDSM4(r, addr) \
    asm volatile("ldmatrix.sync.aligned.m8n8.x4.shared.b16 {%0,%1,%2,%3}, [%4];" \
        : "=r"((r)[0]), "=r"((r)[1]), "=r"((r)[2]), "=r"((r)[3]) : "r"(addr))

__device__ __forceinline__ void mma16816(float* d, const uint32_t* a, const uint32_t* b) {
    asm volatile(
        "mma.sync.aligned.m16n8k16.row.col.f32.bf16.bf16.f32 "
        "{%0,%1,%2,%3}, {%4,%5,%6,%7}, {%8,%9}, {%0,%1,%2,%3};"
        : "+f"(d[0]), "+f"(d[1]), "+f"(d[2]), "+f"(d[3])
        : "r"(a[0]), "r"(a[1]), "r"(a[2]), "r"(a[3]), "r"(b[0]), "r"(b[1]));
}

// swizzled byte offset of 16B chunk c in row r (row = 64 bytes = 4 chunks)
__device__ __forceinline__ uint32_t sw_off(int r, int c) {
    return (uint32_t)(r * 64 + ((c ^ ((r >> 1) & 3)) << 4));
}

// ---------------- scratch (device globals) ----------------
__device__ float g_xz[(size_t)NTOK * 2 * DINNER];     // u_raw (z half unused)
__device__ float g_u[(size_t)NTOK * DINNER];
__device__ float g_zs[(size_t)NTOK * DINNER];
__device__ float g_xdbl[(size_t)NTOK * XDBL_LD];
__device__ float g_delta[(size_t)NTOK * DINNER];
__device__ float g_osplit[(size_t)4 * NTOK * DMODEL]; // split-K buffers for out GEMM
// chunked-scan state
__device__ float g_hend[(size_t)BATCH * DINNER * DSTATE * NCHUNK];
__device__ float g_h0[(size_t)BATCH * DINNER * DSTATE * NCHUNK];
__device__ float g_sumd[(size_t)BATCH * DINNER * NCHUNK];

__device__ __nv_bfloat16 g_xh[(size_t)NTOK * DMODEL],   g_xl[(size_t)NTOK * DMODEL];
__device__ __nv_bfloat16 g_uh[(size_t)NTOK * DINNER],   g_ul[(size_t)NTOK * DINNER];
__device__ __nv_bfloat16 g_yh[(size_t)NTOK * DINNER],   g_yl[(size_t)NTOK * DINNER];
__device__ __nv_bfloat16 g_dth[(size_t)NTOK * DTRANK],  g_dtl[(size_t)NTOK * DTRANK];
// transposed+split weights: [N][K] row-major (K contiguous)
__device__ __nv_bfloat16 g_wint_h[(size_t)2 * DINNER * DMODEL], g_wint_l[(size_t)2 * DINNER * DMODEL];
__device__ __nv_bfloat16 g_wxt_h[(size_t)XDBL_LD * DINNER],     g_wxt_l[(size_t)XDBL_LD * DINNER];
__device__ __nv_bfloat16 g_wdtt_h[(size_t)DINNER * DTRANK],     g_wdtt_l[(size_t)DINNER * DTRANK];
__device__ __nv_bfloat16 g_wot_h[(size_t)DMODEL * DINNER],      g_wot_l[(size_t)DMODEL * DINNER];

// ---------------- mma.sync bf16-split GEMM, 3-stage pipeline ----------------
// C[M,N] = A[M,K] @ B[K,N], A row-major [M][K], B given transposed [N][K].
// EPI 0: store (+zstride per blockIdx.z), 1: softplus(acc+bias), 2: atomicAdd,
// EPI 3: store u-half raw; z-half -> silu to g_zs
#define MG_SMEM (3 * 32768)
template <int EPI>
__global__ __launch_bounds__(256, 2) void mma_gemm(
    const __nv_bfloat16* __restrict__ Ah, const __nv_bfloat16* __restrict__ Al, int lda,
    const __nv_bfloat16* __restrict__ Bh, const __nv_bfloat16* __restrict__ Bl, int ldb,
    float* __restrict__ C, int ldc, int K, int KS, const float* __restrict__ bias,
    int zstride)
{
    extern __shared__ char smem[];
    uint32_t sb = smem_to_u32(smem);
    const int tid = threadIdx.x, lane = tid & 31, wid = tid >> 5;
    const int wm = wid & 3, wn = wid >> 2;          // warp tile: rows wm*32, cols wn*64
    const int row0 = blockIdx.y * 128, col0 = blockIdx.x * 128;
    const int kper = K / KS;
    const int kbeg = blockIdx.z * kper;
    const int kn = kper >> 5;                        // 32-wide k tiles

    float acc[2][8][4];
#pragma unroll
    for (int i = 0; i < 2; i++)
#pragma unroll
        for (int j = 0; j < 8; j++)
#pragma unroll
            for (int r = 0; r < 4; r++) acc[i][j][r] = 0.f;

    auto load_stage = [&](int s, int k0) {
        uint32_t base = sb + s * 32768;
#pragma unroll
        for (int j = 0; j < 2; j++) {
            int idx = tid + j * 256;                 // 0..511
            int r = idx >> 2, c = idx & 3;
            uint32_t so = sw_off(r, c);
            size_t ao = (size_t)(row0 + r) * lda + k0 + c * 8;
            size_t bo = (size_t)(col0 + r) * ldb + k0 + c * 8;
            cpasync16(base + so,          Ah + ao);
            cpasync16(base + 8192 + so,   Al + ao);
            cpasync16(base + 16384 + so,  Bh + bo);
            cpasync16(base + 24576 + so,  Bl + bo);
        }
        CP_COMMIT();
    };

    load_stage(0, kbeg);
    if (kn > 1) load_stage(1, kbeg + 32);

    const int a_row = wm * 32 + ((lane >> 3) & 1) * 8 + (lane & 7);   // + mi*16
    const int b_row = wn * 64 + (lane >> 4) * 8 + (lane & 7);         // + j*16

    for (int it = 0; it < kn; it++) {
        if (it + 1 < kn) CP_WAIT1(); else CP_WAIT0();
        __syncthreads();
        if (it + 2 < kn) load_stage((it + 2) % 3, kbeg + (it + 2) * 32);
        uint32_t base = sb + (it % 3) * 32768;
#pragma unroll
        for (int kk = 0; kk < 2; kk++) {
            uint32_t ah[2][4], al[2][4], bh[8][2], bl[8][2];
#pragma unroll
            for (int mi = 0; mi < 2; mi++) {
                int r = a_row + mi * 16;
                int c = kk * 2 + (lane >> 4);
                uint32_t so = sw_off(r, c);
                LDSM4(ah[mi], base + so);
                LDSM4(al[mi], base + 8192 + so);
            }
#pragma unroll
            for (int j = 0; j < 4; j++) {
                int r = b_row + j * 16;
                int c = kk * 2 + ((lane >> 3) & 1);
                uint32_t so = sw_off(r, c);
                uint32_t t[4];
                LDSM4(t, base + 16384 + so);
                bh[2 * j][0] = t[0]; bh[2 * j][1] = t[1];
                bh[2 * j + 1][0] = t[2]; bh[2 * j + 1][1] = t[3];
                LDSM4(t, base + 24576 + so);
                bl[2 * j][0] = t[0]; bl[2 * j][1] = t[1];
                bl[2 * j + 1][0] = t[2]; bl[2 * j + 1][1] = t[3];
            }
#pragma unroll
            for (int mi = 0; mi < 2; mi++)
#pragma unroll
                for (int nj = 0; nj < 8; nj++) {
                    mma16816(acc[mi][nj], ah[mi], bh[nj]);
                    mma16816(acc[mi][nj], ah[mi], bl[nj]);
                    mma16816(acc[mi][nj], al[mi], bh[nj]);
                }
        }
    }

    if (EPI == 0) C += (size_t)blockIdx.z * zstride;

#pragma unroll
    for (int mi = 0; mi < 2; mi++) {
        int row = row0 + wm * 32 + mi * 16 + (lane >> 2);
#pragma unroll
        for (int nj = 0; nj < 8; nj++) {
            int col = col0 + wn * 64 + nj * 8 + (lane & 3) * 2;
            float* a = acc[mi][nj];
            if (EPI == 0) {
                *(float2*)&C[(size_t)row * ldc + col]       = make_float2(a[0], a[1]);
                *(float2*)&C[(size_t)(row + 8) * ldc + col] = make_float2(a[2], a[3]);
            } else if (EPI == 1) {
                float b0 = bias[col], b1 = bias[col + 1];
                float v0 = a[0] + b0, v1 = a[1] + b1, v2 = a[2] + b0, v3 = a[3] + b1;
                v0 = (v0 > 20.f) ? v0 : log1pf(expf(v0));
                v1 = (v1 > 20.f) ? v1 : log1pf(expf(v1));
                v2 = (v2 > 20.f) ? v2 : log1pf(expf(v2));
                v3 = (v3 > 20.f) ? v3 : log1pf(expf(v3));
                *(float2*)&C[(size_t)row * ldc + col]       = make_float2(v0, v1);
                *(float2*)&C[(size_t)(row + 8) * ldc + col] = make_float2(v2, v3);
            } else if (EPI == 2) {
                atomicAdd(&C[(size_t)row * ldc + col],           a[0]);
                atomicAdd(&C[(size_t)row * ldc + col + 1],       a[1]);
                atomicAdd(&C[(size_t)(row + 8) * ldc + col],     a[2]);
                atomicAdd(&C[(size_t)(row + 8) * ldc + col + 1], a[3]);
            } else {  // EPI == 3: xz epilogue. cols < DINNER raw; cols >= DINNER -> silu -> g_zs
                if (col < DINNER) {
                    *(float2*)&C[(size_t)row * ldc + col]       = make_float2(a[0], a[1]);
                    *(float2*)&C[(size_t)(row + 8) * ldc + col] = make_float2(a[2], a[3]);
                } else {
                    int zc = col - DINNER;
                    float s0 = a[0] / (1.f + __expf(-a[0]));
                    float s1 = a[1] / (1.f + __expf(-a[1]));
                    float s2 = a[2] / (1.f + __expf(-a[2]));
                    float s3 = a[3] / (1.f + __expf(-a[3]));
                    *(float2*)&g_zs[(size_t)row * DINNER + zc]       = make_float2(s0, s1);
                    *(float2*)&g_zs[(size_t)(row + 8) * DINNER + zc] = make_float2(s2, s3);
                }
            }
        }
    }
}

// ---------------- reduce 4 split-K buffers into out ----------------
__global__ void reduce4(const float* __restrict__ src, float* __restrict__ dst, int n4) {
    int i = blockIdx.x * blockDim.x + threadIdx.x;
    if (i >= n4) return;
    const float4* s = (const float4*)src;
    float4 a = s[i], b = s[i + n4], c = s[i + 2 * n4], d = s[i + 3 * n4];
    float4 r = make_float4(a.x + b.x + c.x + d.x, a.y + b.y + c.y + d.y,
                           a.z + b.z + c.z + d.z, a.w + b.w + c.w + d.w);
    ((float4*)dst)[i] = r;
}

// ---------------- elementwise split (fp32 -> bf16 hi/lo) ----------------
__global__ void cvt_split(const float* __restrict__ src,
                          __nv_bfloat16* __restrict__ h, __nv_bfloat16* __restrict__ l, int n)
{
    int i = blockIdx.x * blockDim.x + threadIdx.x;
    if (i >= n) return;
    float v = src[i];
    __nv_bfloat16 hi = __float2bfloat16(v);
    h[i] = hi;
    l[i] = __float2bfloat16(v - __bfloat162float(hi));
}

// dt_lo slice of padded xdbl -> split arrays [2048][64]
__global__ void cvt_dt()
{
    int i = blockIdx.x * blockDim.x + threadIdx.x;   // < NTOK*64
    int t = i >> 6, c = i & 63;
    float v = g_xdbl[(size_t)t * XDBL_LD + c];
    __nv_bfloat16 hi = __float2bfloat16(v);
    g_dth[i] = hi;
    g_dtl[i] = __float2bfloat16(v - __bfloat162float(hi));
}

// ---------------- transpose + split:  W[K][N] -> T[Npad][K] (bf16 hi/lo, pad zero) ----------------
__global__ void transpose_split(const float* __restrict__ W, int K, int N,
                                __nv_bfloat16* __restrict__ Th, __nv_bfloat16* __restrict__ Tl)
{
    __shared__ float t[32][33];
    int bx = blockIdx.x, by = blockIdx.y;
    int tx = threadIdx.x, ty0 = threadIdx.y;
#pragma unroll
    for (int s = 0; s < 4; s++) {
        int ty = ty0 + s * 8;
        int col = bx * 32 + tx;          // n
        int row = by * 32 + ty;          // k
        t[ty][tx] = (col < N) ? W[(size_t)row * N + col] : 0.f;
    }
    __syncthreads();
#pragma unroll
    for (int s = 0; s < 4; s++) {
        int ty = ty0 + s * 8;
        int n = bx * 32 + ty;
        int k = by * 32 + tx;
        float v = t[tx][ty];
        __nv_bfloat16 hi = __float2bfloat16(v);
        Th[(size_t)n * K + k] = hi;
        Tl[(size_t)n * K + k] = __float2bfloat16(v - __bfloat162float(hi));
    }
}

// ---------------- zero fill ----------------
__global__ void zero_kernel(float* __restrict__ p, int n) {
    int i = blockIdx.x * blockDim.x + threadIdx.x;
    if (i < n) p[i] = 0.f;
}

// ---------------- conv + SiLU (+ bf16 split of u) ----------------
__global__ void conv_silu(const float* __restrict__ ck, const float* __restrict__ cb)
{
    int idx = blockIdx.x * blockDim.x + threadIdx.x;
    if (idx >= NTOK * DINNER) return;
    int d  = idx & (DINNER - 1);
    int bt = idx >> 11;
    int t  = bt & (SEQL - 1);

    float acc = cb[d];
#pragma unroll
    for (int w = 0; w < DCONV; w++) {
        int tt = t - (DCONV - 1) + w;
        if (tt >= 0)
            acc = fmaf(ck[w * DINNER + d],
                       g_xz[(size_t)(bt - (DCONV - 1) + w) * (2 * DINNER) + d], acc);
    }
    float u = acc / (1.f + __expf(-acc));
    g_u[idx] = u;
    __nv_bfloat16 hi = __float2bfloat16(u);
    g_uh[idx] = hi;
    g_ul[idx] = __float2bfloat16(u - __bfloat162float(hi));
}

// ---------------- chunked scan: phase 1 (chunk end-states, h0=0) ----------------
__global__ __launch_bounds__(256) void scan_phase1(const float* __restrict__ A_log)
{
    int tid = threadIdx.x;
    int ch = blockIdx.x * 16 + (tid >> 4);   // 0..4095
    int n = tid & 15;
    int c = blockIdx.y;
    int b = ch >> 11;
    int d = ch & (DINNER - 1);

    float a = -expf(A_log[d * DSTATE + n]);
    float h = 0.f, sd = 0.f;

    const float* dptr = g_delta + (size_t)b * SEQL * DINNER + d + (size_t)c * CLEN * DINNER;
    const float* uptr = g_u     + (size_t)b * SEQL * DINNER + d + (size_t)c * CLEN * DINNER;
    const float* xd   = g_xdbl  + (size_t)b * SEQL * XDBL_LD + (size_t)c * CLEN * XDBL_LD;

    for (int t = 0; t < CLEN; t++) {
        float delta = dptr[(size_t)t * DINNER];
        float uv    = uptr[(size_t)t * DINNER];
        float Bn    = xd[t * XDBL_LD + DTRANK + n];
        h = __expf(delta * a) * h + delta * uv * Bn;
        sd += delta;
    }
    size_t idx = ((size_t)(b * DINNER + d) * DSTATE + n);
    g_hend[idx * NCHUNK + c] = h;
    if (n == 0) g_sumd[(size_t)(b * DINNER + d) * NCHUNK + c] = sd;
}

// ---------------- chunked scan: combine (sequential over 8 chunks) ----------------
__global__ void scan_combine(const float* __restrict__ A_log)
{
    int i = blockIdx.x * blockDim.x + threadIdx.x;     // < BATCH*DINNER*DSTATE
    if (i >= BATCH * DINNER * DSTATE) return;
    int n = i & 15;
    int d = (i >> 4) & (DINNER - 1);
    int bd = i >> 4;                                    // b*DINNER + d

    float a = -expf(A_log[d * DSTATE + n]);
    float H = 0.f;
#pragma unroll
    for (int c = 0; c < NCHUNK; c++) {
        g_h0[(size_t)i * NCHUNK + c] = H;
        float S = g_sumd[(size_t)bd * NCHUNK + c];
        H = __expf(a * S) * H + g_hend[(size_t)i * NCHUNK + c];
    }
}

// ---------------- chunked scan: phase 2 (y with true h0) ----------------
__global__ __launch_bounds__(256) void scan_phase2(
    const float* __restrict__ A_log, const float* __restrict__ Dp)
{
    int tid = threadIdx.x;
    int ch = blockIdx.x * 16 + (tid >> 4);
    int n = tid & 15;
    int c = blockIdx.y;
    int b = ch >> 11;
    int d = ch & (DINNER - 1);

    float a = -expf(A_log[d * DSTATE + n]);
    float Dd = Dp[d];
    float h = g_h0[((size_t)(b * DINNER + d) * DSTATE + n) * NCHUNK + c];

    const float* dptr = g_delta + (size_t)b * SEQL * DINNER + d + (size_t)c * CLEN * DINNER;
    const float* uptr = g_u     + (size_t)b * SEQL * DINNER + d + (size_t)c * CLEN * DINNER;
    const float* zptr = g_zs    + (size_t)b * SEQL * DINNER + d + (size_t)c * CLEN * DINNER;
    __nv_bfloat16* yh = g_yh + (size_t)b * SEQL * DINNER + d + (size_t)c * CLEN * DINNER;
    __nv_bfloat16* yl = g_yl + (size_t)b * SEQL * DINNER + d + (size_t)c * CLEN * DINNER;
    const float* xd = g_xdbl + (size_t)b * SEQL * XDBL_LD + (size_t)c * CLEN * XDBL_LD;

    for (int t = 0; t < CLEN; t++) {
        float delta = dptr[(size_t)t * DINNER];
        float uv    = uptr[(size_t)t * DINNER];
        float Bn    = xd[t * XDBL_LD + DTRANK + n];
        float Cn    = xd[t * XDBL_LD + DTRANK + DSTATE + n];

        h = __expf(delta * a) * h + delta * uv * Bn;

        float p = h * Cn;
        p += __shfl_xor_sync(0xffffffffu, p, 8);
        p += __shfl_xor_sync(0xffffffffu, p, 4);
        p += __shfl_xor_sync(0xffffffffu, p, 2);
        p += __shfl_xor_sync(0xffffffffu, p, 1);

        if (n == 0) {
            float v = (p + uv * Dd) * zptr[(size_t)t * DINNER];
            __nv_bfloat16 hi = __float2bfloat16(v);
            yh[(size_t)t * DINNER] = hi;
            yl[(size_t)t * DINNER] = __float2bfloat16(v - __bfloat162float(hi));
        }
    }
}

// ---------------- launch ----------------
extern "C" void kernel_launch(void* const* d_in, const int* in_sizes, int n_in,
                              void* d_out, int out_size)
{
    (void)in_sizes; (void)n_in; (void)out_size;
    const float* x     = (const float*)d_in[0];
    const float* W_in  = (const float*)d_in[1];
    const float* ck    = (const float*)d_in[2];
    const float* cb    = (const float*)d_in[3];
    const float* W_x   = (const float*)d_in[4];
    const float* W_dt  = (const float*)d_in[5];
    const float* b_dt  = (const float*)d_in[6];
    const float* W_out = (const float*)d_in[7];
    const float* A_log = (const float*)d_in[8];
    const float* Dp    = (const float*)d_in[9];
    float* out = (float*)d_out;

    cudaFuncSetAttribute(mma_gemm<0>, cudaFuncAttributeMaxDynamicSharedMemorySize, MG_SMEM);
    cudaFuncSetAttribute(mma_gemm<1>, cudaFuncAttributeMaxDynamicSharedMemorySize, MG_SMEM);
    cudaFuncSetAttribute(mma_gemm<2>, cudaFuncAttributeMaxDynamicSharedMemorySize, MG_SMEM);
    cudaFuncSetAttribute(mma_gemm<3>, cudaFuncAttributeMaxDynamicSharedMemorySize, MG_SMEM);

    float *p_xz, *p_xdbl, *p_delta, *p_osplit;
    cudaGetSymbolAddress((void**)&p_xz,    g_xz);
    cudaGetSymbolAddress((void**)&p_xdbl,  g_xdbl);
    cudaGetSymbolAddress((void**)&p_delta, g_delta);
    cudaGetSymbolAddress((void**)&p_osplit, g_osplit);
    __nv_bfloat16 *xh, *xl, *uh, *ul, *yh, *yl, *dth, *dtl;
    __nv_bfloat16 *winh, *winl, *wxth, *wxtl, *wdtth, *wdttl, *woth, *wotl;
    cudaGetSymbolAddress((void**)&xh, g_xh);     cudaGetSymbolAddress((void**)&xl, g_xl);
    cudaGetSymbolAddress((void**)&uh, g_uh);     cudaGetSymbolAddress((void**)&ul, g_ul);
    cudaGetSymbolAddress((void**)&yh, g_yh);     cudaGetSymbolAddress((void**)&yl, g_yl);
    cudaGetSymbolAddress((void**)&dth, g_dth);   cudaGetSymbolAddress((void**)&dtl, g_dtl);
    cudaGetSymbolAddress((void**)&winh, g_wint_h);  cudaGetSymbolAddress((void**)&winl, g_wint_l);
    cudaGetSymbolAddress((void**)&wxth, g_wxt_h);   cudaGetSymbolAddress((void**)&wxtl, g_wxt_l);
    cudaGetSymbolAddress((void**)&wdtth, g_wdtt_h); cudaGetSymbolAddress((void**)&wdttl, g_wdtt_l);
    cudaGetSymbolAddress((void**)&woth, g_wot_h);   cudaGetSymbolAddress((void**)&wotl, g_wot_l);

    // launch #1..#3: prep
    cvt_split<<<(NTOK * DMODEL + 255) / 256, 256>>>(x, xh, xl, NTOK * DMODEL);
    transpose_split<<<dim3(2 * DINNER / 32, DMODEL / 32), dim3(32, 8)>>>(W_in, DMODEL, 2 * DINNER, winh, winl);
    transpose_split<<<dim3(DMODEL / 32, DINNER / 32), dim3(32, 8)>>>(W_out, DINNER, DMODEL, woth, wotl);

    // launch #4: xz = x @ W_in : M=2048, N=4096, K=1024; z half -> silu -> g_zs
    mma_gemm<3><<<dim3(32, 16, 1), 256, MG_SMEM>>>(
        xh, xl, DMODEL, winh, winl, DMODEL, p_xz, 2 * DINNER, DMODEL, 1, nullptr, 0);

    // conv + silu + u splits
    conv_silu<<<(NTOK * DINNER) / 256, 256>>>(ck, cb);

    // x_dbl = u @ W_x : M=2048, N=128(pad of 96), K=2048, split-K=8 atomics
    zero_kernel<<<(NTOK * XDBL_LD) / 256, 256>>>(p_xdbl, NTOK * XDBL_LD);
    transpose_split<<<dim3(XDBL_LD / 32, DINNER / 32), dim3(32, 8)>>>(W_x, DINNER, DTRANK + 2 * DSTATE, wxth, wxtl);
    mma_gemm<2><<<dim3(1, 16, 8), 256, MG_SMEM>>>(
        uh, ul, DINNER, wxth, wxtl, DINNER, p_xdbl, XDBL_LD, DINNER, 8, nullptr, 0);

    // delta = softplus(dt_lo @ W_dt + b_dt) : M=2048, N=2048, K=64
    cvt_dt<<<(NTOK * DTRANK) / 256, 256>>>();
    transpose_split<<<dim3(DINNER / 32, DTRANK / 32), dim3(32, 8)>>>(W_dt, DTRANK, DINNER, wdtth, wdttl);
    mma_gemm<1><<<dim3(16, 16, 1), 256, MG_SMEM>>>(
        dth, dtl, DTRANK, wdtth, wdttl, DTRANK, p_delta, DINNER, DTRANK, 1, b_dt, 0);

    // chunked selective scan
    scan_phase1<<<dim3((BATCH * DINNER) / 16, NCHUNK), 256>>>(A_log);
    scan_combine<<<(BATCH * DINNER * DSTATE) / 256, 256>>>(A_log);
    scan_phase2<<<dim3((BATCH * DINNER) / 16, NCHUNK), 256>>>(A_log, Dp);

    // out = y @ W_out : M=2048, N=1024, K=2048, split-K=4 -> buffers -> reduce
    mma_gemm<0><<<dim3(8, 16, 4), 256, MG_SMEM>>>(
        yh, yl, DINNER, woth, wotl, DINNER, p_osplit, DMODEL, DINNER, 4, nullptr, NTOK * DMODEL);
    reduce4<<<(NTOK * DMODEL / 4 + 255) / 256, 256>>>(p_osplit, out, NTOK * DMODEL / 4);
}

// round 7
// speedup vs baseline: 3.2578x; 1.1659x over previous
#include <cuda_runtime.h>
#include <cuda_fp16.h>
#include <math.h>
#include <stdint.h>

// ---------------- problem constants ----------------
#define BATCH   2
#define SEQL    1024
#define DMODEL  1024
#define DINNER  2048
#define DSTATE  16
#define DCONV   4
#define DTRANK  64
#define NTOK    (BATCH * SEQL)          // 2048
#define XDBL_LD 128                     // padded (dt 0..63 | B 64..79 | C 80..95 | pad)
#define NCHUNK  8
#define CLEN    (SEQL / NCHUNK)         // 128

// ---------------- PTX helpers (portable: sm_80-era features only) ----------------
__device__ __forceinline__ uint32_t smem_to_u32(const void* p) {
    uint32_t a;
    asm("{ .reg .u64 t; cvta.to.shared.u64 t, %1; cvt.u32.u64 %0, t; }" : "=r"(a) : "l"(p));
    return a;
}
__device__ __forceinline__ void cpasync16(uint32_t s, const void* g) {
    asm volatile("cp.async.cg.shared.global [%0], [%1], 16;" :: "r"(s), "l"(g));
}
#define CP_COMMIT()  asm volatile("cp.async.commit_group;" ::: "memory")
#define CP_WAIT0()   asm volatile("cp.async.wait_group 0;" ::: "memory")
#define CP_WAIT1()   asm volatile("cp.async.wait_group 1;" ::: "memory")
#define LDSM4(r, addr) \
    asm volatile("ldmatrix.sync.aligned.m8n8.x4.shared.b16 {%0,%1,%2,%3}, [%4];" \
        : "=r"((r)[0]), "=r"((r)[1]), "=r"((r)[2]), "=r"((r)[3]) : "r"(addr))

__device__ __forceinline__ void mma16816(float* d, const uint32_t* a, const uint32_t* b) {
    asm volatile(
        "mma.sync.aligned.m16n8k16.row.col.f32.f16.f16.f32 "
        "{%0,%1,%2,%3}, {%4,%5,%6,%7}, {%8,%9}, {%0,%1,%2,%3};"
        : "+f"(d[0]), "+f"(d[1]), "+f"(d[2]), "+f"(d[3])
        : "r"(a[0]), "r"(a[1]), "r"(a[2]), "r"(a[3]), "r"(b[0]), "r"(b[1]));
}

// swizzled byte offset of 16B chunk c in row r (row = 64 bytes = 4 chunks)
__device__ __forceinline__ uint32_t sw_off(int r, int c) {
    return (uint32_t)(r * 64 + ((c ^ ((r >> 1) & 3)) << 4));
}

// ---------------- scratch (device globals) ----------------
__device__ float g_xz[(size_t)NTOK * 2 * DINNER];     // u_raw (z half unused)
__device__ float g_u[(size_t)NTOK * DINNER];
__device__ float g_zs[(size_t)NTOK * DINNER];
__device__ float g_xdbl[(size_t)NTOK * XDBL_LD];
__device__ float g_delta[(size_t)NTOK * DINNER];
__device__ float g_osplit[(size_t)4 * NTOK * DMODEL]; // split-K buffers for out GEMM
// chunked-scan state
__device__ float g_hend[(size_t)BATCH * DINNER * DSTATE * NCHUNK];
__device__ float g_h0[(size_t)BATCH * DINNER * DSTATE * NCHUNK];
__device__ float g_sumd[(size_t)BATCH * DINNER * NCHUNK];

// A-side: fp16 two-term split (hi + lo ~ 22 mantissa bits)
__device__ __half g_xh[(size_t)NTOK * DMODEL],   g_xl[(size_t)NTOK * DMODEL];
__device__ __half g_uh[(size_t)NTOK * DINNER],   g_ul[(size_t)NTOK * DINNER];
__device__ __half g_yh[(size_t)NTOK * DINNER],   g_yl[(size_t)NTOK * DINNER];
__device__ __half g_dth[(size_t)NTOK * DTRANK],  g_dtl[(size_t)NTOK * DTRANK];
// B-side: transposed single fp16 weights: [N][K] row-major (K contiguous)
__device__ __half g_wint[(size_t)2 * DINNER * DMODEL];
__device__ __half g_wxt[(size_t)XDBL_LD * DINNER];
__device__ __half g_wdtt[(size_t)DINNER * DTRANK];
__device__ __half g_wot[(size_t)DMODEL * DINNER];

// ---------------- mma.sync fp16 2-pass GEMM, 3-stage pipeline ----------------
// C[M,N] = (Ah+Al)[M,K] @ B[K,N], B given transposed [N][K], fp32 accum.
// EPI 0: store (+zstride per blockIdx.z), 1: softplus(acc+bias), 2: atomicAdd,
// EPI 3: store u-half raw; z-half -> silu to g_zs
#define STAGE_B 24576
#define MG_SMEM (3 * STAGE_B)
template <int EPI>
__global__ __launch_bounds__(256, 2) void mma_gemm(
    const __half* __restrict__ Ah, const __half* __restrict__ Al, int lda,
    const __half* __restrict__ B, int ldb,
    float* __restrict__ C, int ldc, int K, int KS, const float* __restrict__ bias,
    int zstride)
{
    extern __shared__ char smem[];
    uint32_t sb = smem_to_u32(smem);
    const int tid = threadIdx.x, lane = tid & 31, wid = tid >> 5;
    const int wm = wid & 3, wn = wid >> 2;          // warp tile: rows wm*32, cols wn*64
    const int row0 = blockIdx.y * 128, col0 = blockIdx.x * 128;
    const int kper = K / KS;
    const int kbeg = blockIdx.z * kper;
    const int kn = kper >> 5;                        // 32-wide k tiles

    float acc[2][8][4];
#pragma unroll
    for (int i = 0; i < 2; i++)
#pragma unroll
        for (int j = 0; j < 8; j++)
#pragma unroll
            for (int r = 0; r < 4; r++) acc[i][j][r] = 0.f;

    // stage layout: Ah 0..8K, Al 8K..16K, B 16K..24K
    auto load_stage = [&](int s, int k0) {
        uint32_t base = sb + s * STAGE_B;
#pragma unroll
        for (int j = 0; j < 2; j++) {
            int idx = tid + j * 256;                 // 0..511
            int r = idx >> 2, c = idx & 3;
            uint32_t so = sw_off(r, c);
            size_t ao = (size_t)(row0 + r) * lda + k0 + c * 8;
            size_t bo = (size_t)(col0 + r) * ldb + k0 + c * 8;
            cpasync16(base + so,          Ah + ao);
            cpasync16(base + 8192 + so,   Al + ao);
            cpasync16(base + 16384 + so,  B + bo);
        }
        CP_COMMIT();
    };

    load_stage(0, kbeg);
    if (kn > 1) load_stage(1, kbeg + 32);

    const int a_row = wm * 32 + ((lane >> 3) & 1) * 8 + (lane & 7);   // + mi*16
    const int b_row = wn * 64 + (lane >> 4) * 8 + (lane & 7);         // + j*16

    for (int it = 0; it < kn; it++) {
        if (it + 1 < kn) CP_WAIT1(); else CP_WAIT0();
        __syncthreads();
        if (it + 2 < kn) load_stage((it + 2) % 3, kbeg + (it + 2) * 32);
        uint32_t base = sb + (it % 3) * STAGE_B;
#pragma unroll
        for (int kk = 0; kk < 2; kk++) {
            uint32_t ah[2][4], al[2][4], bb[8][2];
#pragma unroll
            for (int mi = 0; mi < 2; mi++) {
                int r = a_row + mi * 16;
                int c = kk * 2 + (lane >> 4);
                uint32_t so = sw_off(r, c);
                LDSM4(ah[mi], base + so);
                LDSM4(al[mi], base + 8192 + so);
            }
#pragma unroll
            for (int j = 0; j < 4; j++) {
                int r = b_row + j * 16;
                int c = kk * 2 + ((lane >> 3) & 1);
                uint32_t so = sw_off(r, c);
                uint32_t t[4];
                LDSM4(t, base + 16384 + so);
                bb[2 * j][0] = t[0]; bb[2 * j][1] = t[1];
                bb[2 * j + 1][0] = t[2]; bb[2 * j + 1][1] = t[3];
            }
#pragma unroll
            for (int mi = 0; mi < 2; mi++)
#pragma unroll
                for (int nj = 0; nj < 8; nj++) {
                    mma16816(acc[mi][nj], ah[mi], bb[nj]);
                    mma16816(acc[mi][nj], al[mi], bb[nj]);
                }
        }
    }

    if (EPI == 0) C += (size_t)blockIdx.z * zstride;

#pragma unroll
    for (int mi = 0; mi < 2; mi++) {
        int row = row0 + wm * 32 + mi * 16 + (lane >> 2);
#pragma unroll
        for (int nj = 0; nj < 8; nj++) {
            int col = col0 + wn * 64 + nj * 8 + (lane & 3) * 2;
            float* a = acc[mi][nj];
            if (EPI == 0) {
                *(float2*)&C[(size_t)row * ldc + col]       = make_float2(a[0], a[1]);
                *(float2*)&C[(size_t)(row + 8) * ldc + col] = make_float2(a[2], a[3]);
            } else if (EPI == 1) {
                float b0 = bias[col], b1 = bias[col + 1];
                float v0 = a[0] + b0, v1 = a[1] + b1, v2 = a[2] + b0, v3 = a[3] + b1;
                v0 = (v0 > 20.f) ? v0 : log1pf(expf(v0));
                v1 = (v1 > 20.f) ? v1 : log1pf(expf(v1));
                v2 = (v2 > 20.f) ? v2 : log1pf(expf(v2));
                v3 = (v3 > 20.f) ? v3 : log1pf(expf(v3));
                *(float2*)&C[(size_t)row * ldc + col]       = make_float2(v0, v1);
                *(float2*)&C[(size_t)(row + 8) * ldc + col] = make_float2(v2, v3);
            } else if (EPI == 2) {
                atomicAdd(&C[(size_t)row * ldc + col],           a[0]);
                atomicAdd(&C[(size_t)row * ldc + col + 1],       a[1]);
                atomicAdd(&C[(size_t)(row + 8) * ldc + col],     a[2]);
                atomicAdd(&C[(size_t)(row + 8) * ldc + col + 1], a[3]);
            } else {  // EPI == 3: xz epilogue. cols < DINNER raw; cols >= DINNER -> silu -> g_zs
                if (col < DINNER) {
                    *(float2*)&C[(size_t)row * ldc + col]       = make_float2(a[0], a[1]);
                    *(float2*)&C[(size_t)(row + 8) * ldc + col] = make_float2(a[2], a[3]);
                } else {
                    int zc = col - DINNER;
                    float s0 = a[0] / (1.f + __expf(-a[0]));
                    float s1 = a[1] / (1.f + __expf(-a[1]));
                    float s2 = a[2] / (1.f + __expf(-a[2]));
                    float s3 = a[3] / (1.f + __expf(-a[3]));
                    *(float2*)&g_zs[(size_t)row * DINNER + zc]       = make_float2(s0, s1);
                    *(float2*)&g_zs[(size_t)(row + 8) * DINNER + zc] = make_float2(s2, s3);
                }
            }
        }
    }
}

// ---------------- reduce 4 split-K buffers into out ----------------
__global__ void reduce4(const float* __restrict__ src, float* __restrict__ dst, int n4) {
    int i = blockIdx.x * blockDim.x + threadIdx.x;
    if (i >= n4) return;
    const float4* s = (const float4*)src;
    float4 a = s[i], b = s[i + n4], c = s[i + 2 * n4], d = s[i + 3 * n4];
    float4 r = make_float4(a.x + b.x + c.x + d.x, a.y + b.y + c.y + d.y,
                           a.z + b.z + c.z + d.z, a.w + b.w + c.w + d.w);
    ((float4*)dst)[i] = r;
}

// ---------------- elementwise split (fp32 -> fp16 hi/lo) ----------------
__global__ void cvt_split(const float* __restrict__ src,
                          __half* __restrict__ h, __half* __restrict__ l, int n)
{
    int i = blockIdx.x * blockDim.x + threadIdx.x;
    if (i >= n) return;
    float v = src[i];
    __half hi = __float2half_rn(v);
    h[i] = hi;
    l[i] = __float2half_rn(v - __half2float(hi));
}

// dt_lo slice of padded xdbl -> split arrays [2048][64]
__global__ void cvt_dt()
{
    int i = blockIdx.x * blockDim.x + threadIdx.x;   // < NTOK*64
    int t = i >> 6, c = i & 63;
    float v = g_xdbl[(size_t)t * XDBL_LD + c];
    __half hi = __float2half_rn(v);
    g_dth[i] = hi;
    g_dtl[i] = __float2half_rn(v - __half2float(hi));
}

// ---------------- transpose + convert:  W[K][N] -> T[Npad][K] (fp16, pad zero) ----------------
__global__ void transpose_cvt(const float* __restrict__ W, int K, int N,
                              __half* __restrict__ T)
{
    __shared__ float t[32][33];
    int bx = blockIdx.x, by = blockIdx.y;
    int tx = threadIdx.x, ty0 = threadIdx.y;
#pragma unroll
    for (int s = 0; s < 4; s++) {
        int ty = ty0 + s * 8;
        int col = bx * 32 + tx;          // n
        int row = by * 32 + ty;          // k
        t[ty][tx] = (col < N) ? W[(size_t)row * N + col] : 0.f;
    }
    __syncthreads();
#pragma unroll
    for (int s = 0; s < 4; s++) {
        int ty = ty0 + s * 8;
        int n = bx * 32 + ty;
        int k = by * 32 + tx;
        T[(size_t)n * K + k] = __float2half_rn(t[tx][ty]);
    }
}

// ---------------- zero fill ----------------
__global__ void zero_kernel(float* __restrict__ p, int n) {
    int i = blockIdx.x * blockDim.x + threadIdx.x;
    if (i < n) p[i] = 0.f;
}

// ---------------- conv + SiLU (+ fp16 split of u) ----------------
__global__ void conv_silu(const float* __restrict__ ck, const float* __restrict__ cb)
{
    int idx = blockIdx.x * blockDim.x + threadIdx.x;
    if (idx >= NTOK * DINNER) return;
    int d  = idx & (DINNER - 1);
    int bt = idx >> 11;
    int t  = bt & (SEQL - 1);

    float acc = cb[d];
#pragma unroll
    for (int w = 0; w < DCONV; w++) {
        int tt = t - (DCONV - 1) + w;
        if (tt >= 0)
            acc = fmaf(ck[w * DINNER + d],
                       g_xz[(size_t)(bt - (DCONV - 1) + w) * (2 * DINNER) + d], acc);
    }
    float u = acc / (1.f + __expf(-acc));
    g_u[idx] = u;
    __half hi = __float2half_rn(u);
    g_uh[idx] = hi;
    g_ul[idx] = __float2half_rn(u - __half2float(hi));
}

// ---------------- chunked scan: phase 1 (chunk end-states, h0=0) ----------------
__global__ __launch_bounds__(256) void scan_phase1(const float* __restrict__ A_log)
{
    int tid = threadIdx.x;
    int ch = blockIdx.x * 16 + (tid >> 4);   // 0..4095
    int n = tid & 15;
    int c = blockIdx.y;
    int b = ch >> 11;
    int d = ch & (DINNER - 1);

    float a = -expf(A_log[d * DSTATE + n]);
    float h = 0.f, sd = 0.f;

    const float* dptr = g_delta + (size_t)b * SEQL * DINNER + d + (size_t)c * CLEN * DINNER;
    const float* uptr = g_u     + (size_t)b * SEQL * DINNER + d + (size_t)c * CLEN * DINNER;
    const float* xd   = g_xdbl  + (size_t)b * SEQL * XDBL_LD + (size_t)c * CLEN * XDBL_LD;

    for (int t = 0; t < CLEN; t++) {
        float delta = dptr[(size_t)t * DINNER];
        float uv    = uptr[(size_t)t * DINNER];
        float Bn    = xd[t * XDBL_LD + DTRANK + n];
        h = __expf(delta * a) * h + delta * uv * Bn;
        sd += delta;
    }
    size_t idx = ((size_t)(b * DINNER + d) * DSTATE + n);
    g_hend[idx * NCHUNK + c] = h;
    if (n == 0) g_sumd[(size_t)(b * DINNER + d) * NCHUNK + c] = sd;
}

// ---------------- chunked scan: combine (sequential over 8 chunks) ----------------
__global__ void scan_combine(const float* __restrict__ A_log)
{
    int i = blockIdx.x * blockDim.x + threadIdx.x;     // < BATCH*DINNER*DSTATE
    if (i >= BATCH * DINNER * DSTATE) return;
    int n = i & 15;
    int d = (i >> 4) & (DINNER - 1);
    int bd = i >> 4;                                    // b*DINNER + d

    float a = -expf(A_log[d * DSTATE + n]);
    float H = 0.f;
#pragma unroll
    for (int c = 0; c < NCHUNK; c++) {
        g_h0[(size_t)i * NCHUNK + c] = H;
        float S = g_sumd[(size_t)bd * NCHUNK + c];
        H = __expf(a * S) * H + g_hend[(size_t)i * NCHUNK + c];
    }
}

// ---------------- chunked scan: phase 2 (y with true h0) ----------------
__global__ __launch_bounds__(256) void scan_phase2(
    const float* __restrict__ A_log, const float* __restrict__ Dp)
{
    int tid = threadIdx.x;
    int ch = blockIdx.x * 16 + (tid >> 4);
    int n = tid & 15;
    int c = blockIdx.y;
    int b = ch >> 11;
    int d = ch & (DINNER - 1);

    float a = -expf(A_log[d * DSTATE + n]);
    float Dd = Dp[d];
    float h = g_h0[((size_t)(b * DINNER + d) * DSTATE + n) * NCHUNK + c];

    const float* dptr = g_delta + (size_t)b * SEQL * DINNER + d + (size_t)c * CLEN * DINNER;
    const float* uptr = g_u     + (size_t)b * SEQL * DINNER + d + (size_t)c * CLEN * DINNER;
    const float* zptr = g_zs    + (size_t)b * SEQL * DINNER + d + (size_t)c * CLEN * DINNER;
    __half* yh = g_yh + (size_t)b * SEQL * DINNER + d + (size_t)c * CLEN * DINNER;
    __half* yl = g_yl + (size_t)b * SEQL * DINNER + d + (size_t)c * CLEN * DINNER;
    const float* xd = g_xdbl + (size_t)b * SEQL * XDBL_LD + (size_t)c * CLEN * XDBL_LD;

    for (int t = 0; t < CLEN; t++) {
        float delta = dptr[(size_t)t * DINNER];
        float uv    = uptr[(size_t)t * DINNER];
        float Bn    = xd[t * XDBL_LD + DTRANK + n];
        float Cn    = xd[t * XDBL_LD + DTRANK + DSTATE + n];

        h = __expf(delta * a) * h + delta * uv * Bn;

        float p = h * Cn;
        p += __shfl_xor_sync(0xffffffffu, p, 8);
        p += __shfl_xor_sync(0xffffffffu, p, 4);
        p += __shfl_xor_sync(0xffffffffu, p, 2);
        p += __shfl_xor_sync(0xffffffffu, p, 1);

        if (n == 0) {
            float v = (p + uv * Dd) * zptr[(size_t)t * DINNER];
            __half hi = __float2half_rn(v);
            yh[(size_t)t * DINNER] = hi;
            yl[(size_t)t * DINNER] = __float2half_rn(v - __half2float(hi));
        }
    }
}

// ---------------- launch ----------------
extern "C" void kernel_launch(void* const* d_in, const int* in_sizes, int n_in,
                              void* d_out, int out_size)
{
    (void)in_sizes; (void)n_in; (void)out_size;
    const float* x     = (const float*)d_in[0];
    const float* W_in  = (const float*)d_in[1];
    const float* ck    = (const float*)d_in[2];
    const float* cb    = (const float*)d_in[3];
    const float* W_x   = (const float*)d_in[4];
    const float* W_dt  = (const float*)d_in[5];
    const float* b_dt  = (const float*)d_in[6];
    const float* W_out = (const float*)d_in[7];
    const float* A_log = (const float*)d_in[8];
    const float* Dp    = (const float*)d_in[9];
    float* out = (float*)d_out;

    cudaFuncSetAttribute(mma_gemm<0>, cudaFuncAttributeMaxDynamicSharedMemorySize, MG_SMEM);
    cudaFuncSetAttribute(mma_gemm<1>, cudaFuncAttributeMaxDynamicSharedMemorySize, MG_SMEM);
    cudaFuncSetAttribute(mma_gemm<2>, cudaFuncAttributeMaxDynamicSharedMemorySize, MG_SMEM);
    cudaFuncSetAttribute(mma_gemm<3>, cudaFuncAttributeMaxDynamicSharedMemorySize, MG_SMEM);

    float *p_xz, *p_xdbl, *p_delta, *p_osplit;
    cudaGetSymbolAddress((void**)&p_xz,    g_xz);
    cudaGetSymbolAddress((void**)&p_xdbl,  g_xdbl);
    cudaGetSymbolAddress((void**)&p_delta, g_delta);
    cudaGetSymbolAddress((void**)&p_osplit, g_osplit);
    __half *xh, *xl, *uh, *ul, *yh, *yl, *dth, *dtl;
    __half *wint, *wxt, *wdtt, *wot;
    cudaGetSymbolAddress((void**)&xh, g_xh);     cudaGetSymbolAddress((void**)&xl, g_xl);
    cudaGetSymbolAddress((void**)&uh, g_uh);     cudaGetSymbolAddress((void**)&ul, g_ul);
    cudaGetSymbolAddress((void**)&yh, g_yh);     cudaGetSymbolAddress((void**)&yl, g_yl);
    cudaGetSymbolAddress((void**)&dth, g_dth);   cudaGetSymbolAddress((void**)&dtl, g_dtl);
    cudaGetSymbolAddress((void**)&wint, g_wint);
    cudaGetSymbolAddress((void**)&wxt, g_wxt);
    cudaGetSymbolAddress((void**)&wdtt, g_wdtt);
    cudaGetSymbolAddress((void**)&wot, g_wot);

    // launch #1..#3: prep
    cvt_split<<<(NTOK * DMODEL + 255) / 256, 256>>>(x, xh, xl, NTOK * DMODEL);
    transpose_cvt<<<dim3(2 * DINNER / 32, DMODEL / 32), dim3(32, 8)>>>(W_in, DMODEL, 2 * DINNER, wint);
    transpose_cvt<<<dim3(DMODEL / 32, DINNER / 32), dim3(32, 8)>>>(W_out, DINNER, DMODEL, wot);

    // launch #4: xz = x @ W_in : M=2048, N=4096, K=1024; z half -> silu -> g_zs
    mma_gemm<3><<<dim3(32, 16, 1), 256, MG_SMEM>>>(
        xh, xl, DMODEL, wint, DMODEL, p_xz, 2 * DINNER, DMODEL, 1, nullptr, 0);

    // conv + silu + u splits
    conv_silu<<<(NTOK * DINNER) / 256, 256>>>(ck, cb);

    // x_dbl = u @ W_x : M=2048, N=128(pad of 96), K=2048, split-K=8 atomics
    zero_kernel<<<(NTOK * XDBL_LD) / 256, 256>>>(p_xdbl, NTOK * XDBL_LD);
    transpose_cvt<<<dim3(XDBL_LD / 32, DINNER / 32), dim3(32, 8)>>>(W_x, DINNER, DTRANK + 2 * DSTATE, wxt);
    mma_gemm<2><<<dim3(1, 16, 8), 256, MG_SMEM>>>(
        uh, ul, DINNER, wxt, DINNER, p_xdbl, XDBL_LD, DINNER, 8, nullptr, 0);

    // delta = softplus(dt_lo @ W_dt + b_dt) : M=2048, N=2048, K=64
    cvt_dt<<<(NTOK * DTRANK) / 256, 256>>>();
    transpose_cvt<<<dim3(DINNER / 32, DTRANK / 32), dim3(32, 8)>>>(W_dt, DTRANK, DINNER, wdtt);
    mma_gemm<1><<<dim3(16, 16, 1), 256, MG_SMEM>>>(
        dth, dtl, DTRANK, wdtt, DTRANK, p_delta, DINNER, DTRANK, 1, b_dt, 0);

    // chunked selective scan
    scan_phase1<<<dim3((BATCH * DINNER) / 16, NCHUNK), 256>>>(A_log);
    scan_combine<<<(BATCH * DINNER * DSTATE) / 256, 256>>>(A_log);
    scan_phase2<<<dim3((BATCH * DINNER) / 16, NCHUNK), 256>>>(A_log, Dp);

    // out = y @ W_out : M=2048, N=1024, K=2048, split-K=4 -> buffers -> reduce
    mma_gemm<0><<<dim3(8, 16, 4), 256, MG_SMEM>>>(
        yh, yl, DINNER, wot, DINNER, p_osplit, DMODEL, DINNER, 4, nullptr, NTOK * DMODEL);
    reduce4<<<(NTOK * DMODEL / 4 + 255) / 256, 256>>>(p_osplit, out, NTOK * DMODEL / 4);
}